// round 13
// baseline (speedup 1.0000x reference)
#include <cuda_runtime.h>
#include <math.h>

// ---------------- problem constants ----------------
#define B_   8
#define S_   1024
#define E_   512
#define H_   8
#define D_   64
#define L_   4
#define KTOP 256
#define FIN  128
#define NCLS 10
#define QT   32

// ---------------- device scratch ----------------
__device__ float g_o [(size_t)B_ * S_ * E_];
__device__ float g_qh[(size_t)B_ * S_ * E_];
__device__ float g_ql[(size_t)B_ * S_ * E_];
__device__ float g_k [(size_t)B_ * S_ * E_];
__device__ float g_v [(size_t)B_ * S_ * E_];
__device__ float g_pool[B_ * E_];
__device__ float g_zero[E_];                       // zero-initialized
// combined weights/biases
__device__ float g_cw0[3 * FIN * E_];              // layer0: emb_w @ W{q,k,v}0
__device__ float g_cw [9 * E_ * E_];               // layers1-3: Wo_{l-1} @ W{q,k,v}_l
__device__ float g_cb [12 * E_];                   // combined biases [l*3+j]
__device__ float g_fcw[E_ * NCLS];                 // Wo3 @ fc_w
__device__ float g_fcb[NCLS];                      // bo3 @ fc_w + fc_b

// ---------------- helpers ----------------
__device__ __forceinline__ float tf32f(float x) {
    unsigned u;
    asm("cvt.rna.tf32.f32 %0, %1;" : "=r"(u) : "f"(x));
    return __uint_as_float(u);
}
__device__ __forceinline__ void mma_tf32(float c[4],
    unsigned a0, unsigned a1, unsigned a2, unsigned a3,
    unsigned b0, unsigned b1)
{
    asm volatile(
        "mma.sync.aligned.m16n8k8.row.col.f32.tf32.tf32.f32 "
        "{%0,%1,%2,%3},{%4,%5,%6,%7},{%8,%9},{%0,%1,%2,%3};"
        : "+f"(c[0]), "+f"(c[1]), "+f"(c[2]), "+f"(c[3])
        : "r"(a0), "r"(a1), "r"(a2), "r"(a3), "r"(b0), "r"(b1));
}
__device__ __forceinline__ unsigned fu(float x) { return __float_as_uint(x); }

__device__ __forceinline__ unsigned fmap(float x) {
    unsigned u = __float_as_uint(x);
    return (u & 0x80000000u) ? ~u : (u | 0x80000000u);
}
__device__ __forceinline__ float unfmap(unsigned u) {
    return (u & 0x80000000u) ? __uint_as_float(u & 0x7FFFFFFFu)
                             : __uint_as_float(~u);
}
__device__ __forceinline__ void split2(float x, float& h, float& l) {
    h = tf32f(x);
    l = tf32f(x - h);
}

// ======================================================================
// split-tf32 GEMM, 128x128 tile (for weight folding).
// ======================================================================
#define GA 36
#define GB 136
#define GEMM_SMEM ((128*GA*2 + 32*GB*2) * 4)   // 71680 bytes

__device__ __forceinline__
void gemm_body(const float* __restrict__ A, const float* __restrict__ W,
               const float* __restrict__ bias,
               float* __restrict__ Ch, float* __restrict__ Cl, float scale,
               int M, int K, int N)
{
    extern __shared__ float gsm[];
    float* Ash = gsm;
    float* Asl = Ash + 128 * GA;
    float* Bsh = Asl + 128 * GA;
    float* Bsl = Bsh + 32 * GB;

    const int t    = threadIdx.x;
    const int m0   = blockIdx.y * 128;
    const int n0   = blockIdx.x * 128;
    const int w    = t >> 5;
    const int lane = t & 31;
    const int wm   = w >> 2;
    const int wn   = w & 3;
    const int grp  = lane >> 2;
    const int tg   = lane & 3;

    float acc[4][4][4];
#pragma unroll
    for (int i = 0; i < 4; ++i)
#pragma unroll
        for (int j = 0; j < 4; ++j)
#pragma unroll
            for (int c = 0; c < 4; ++c) acc[i][j][c] = 0.f;

    const float* Aptr = A + (size_t)m0 * K;
    const float* Wptr = W + n0;

    for (int k0 = 0; k0 < K; k0 += 32) {
#pragma unroll
        for (int i = 0; i < 4; ++i) {
            int idx = t + i * 256;
            int row = idx >> 3;
            int c4  = (idx & 7) * 4;
            float4 v = *(const float4*)(Aptr + (size_t)row * K + k0 + c4);
            float h0, l0, h1, l1, h2, l2, h3, l3;
            split2(v.x, h0, l0); split2(v.y, h1, l1);
            split2(v.z, h2, l2); split2(v.w, h3, l3);
            *(float4*)&Ash[row * GA + c4] = make_float4(h0, h1, h2, h3);
            *(float4*)&Asl[row * GA + c4] = make_float4(l0, l1, l2, l3);
        }
#pragma unroll
        for (int i = 0; i < 4; ++i) {
            int idx = t + i * 256;
            int row = idx >> 5;
            int c4  = (idx & 31) * 4;
            float4 v = *(const float4*)(Wptr + (size_t)(k0 + row) * N + c4);
            float h0, l0, h1, l1, h2, l2, h3, l3;
            split2(v.x, h0, l0); split2(v.y, h1, l1);
            split2(v.z, h2, l2); split2(v.w, h3, l3);
            *(float4*)&Bsh[row * GB + c4] = make_float4(h0, h1, h2, h3);
            *(float4*)&Bsl[row * GB + c4] = make_float4(l0, l1, l2, l3);
        }
        __syncthreads();

#pragma unroll
        for (int ks = 0; ks < 4; ++ks) {
            const int ka = ks * 8 + tg;
            unsigned bh[4][2], bl[4][2];
#pragma unroll
            for (int nt = 0; nt < 4; ++nt) {
                int c = wn * 32 + nt * 8 + grp;
                bh[nt][0] = fu(Bsh[ka * GB + c]);
                bh[nt][1] = fu(Bsh[(ka + 4) * GB + c]);
                bl[nt][0] = fu(Bsl[ka * GB + c]);
                bl[nt][1] = fu(Bsl[(ka + 4) * GB + c]);
            }
#pragma unroll
            for (int mt = 0; mt < 4; ++mt) {
                int r = wm * 64 + mt * 16 + grp;
                unsigned ah0 = fu(Ash[r * GA + ka]);
                unsigned ah1 = fu(Ash[(r + 8) * GA + ka]);
                unsigned ah2 = fu(Ash[r * GA + ka + 4]);
                unsigned ah3 = fu(Ash[(r + 8) * GA + ka + 4]);
                unsigned al0 = fu(Asl[r * GA + ka]);
                unsigned al1 = fu(Asl[(r + 8) * GA + ka]);
                unsigned al2 = fu(Asl[r * GA + ka + 4]);
                unsigned al3 = fu(Asl[(r + 8) * GA + ka + 4]);
#pragma unroll
                for (int nt = 0; nt < 4; ++nt) {
                    mma_tf32(acc[mt][nt], ah0, ah1, ah2, ah3, bh[nt][0], bh[nt][1]);
                    mma_tf32(acc[mt][nt], ah0, ah1, ah2, ah3, bl[nt][0], bl[nt][1]);
                    mma_tf32(acc[mt][nt], al0, al1, al2, al3, bh[nt][0], bh[nt][1]);
                }
            }
        }
        __syncthreads();
    }

    if (Cl == nullptr) {
#pragma unroll
        for (int nt = 0; nt < 4; ++nt) {
            const int c = n0 + wn * 32 + nt * 8 + 2 * tg;
            float2 bv = *(const float2*)&bias[c];
#pragma unroll
            for (int mt = 0; mt < 4; ++mt) {
                int r = m0 + wm * 64 + mt * 16 + grp;
                float2 r0 = make_float2(acc[mt][nt][0] + bv.x, acc[mt][nt][1] + bv.y);
                float2 r1 = make_float2(acc[mt][nt][2] + bv.x, acc[mt][nt][3] + bv.y);
                *(float2*)&Ch[(size_t)r * N + c]       = r0;
                *(float2*)&Ch[(size_t)(r + 8) * N + c] = r1;
            }
        }
    } else {
#pragma unroll
        for (int nt = 0; nt < 4; ++nt) {
            const int c = n0 + wn * 32 + nt * 8 + 2 * tg;
            float2 bv = *(const float2*)&bias[c];
#pragma unroll
            for (int mt = 0; mt < 4; ++mt) {
                int r = m0 + wm * 64 + mt * 16 + grp;
                float v00 = (acc[mt][nt][0] + bv.x) * scale;
                float v01 = (acc[mt][nt][1] + bv.y) * scale;
                float v10 = (acc[mt][nt][2] + bv.x) * scale;
                float v11 = (acc[mt][nt][3] + bv.y) * scale;
                float h00, l00, h01, l01, h10, l10, h11, l11;
                split2(v00, h00, l00); split2(v01, h01, l01);
                split2(v10, h10, l10); split2(v11, h11, l11);
                *(float2*)&Ch[(size_t)r * N + c]       = make_float2(h00, h01);
                *(float2*)&Ch[(size_t)(r + 8) * N + c] = make_float2(h10, h11);
                *(float2*)&Cl[(size_t)r * N + c]       = make_float2(l00, l01);
                *(float2*)&Cl[(size_t)(r + 8) * N + c] = make_float2(l10, l11);
            }
        }
    }
}

// ======================================================================
// split-tf32 GEMM, 64x128 tile (QKV path — better wave quantization).
// 256 threads = 8 warps (2m x 4n), warp tile 32x32.
// ======================================================================
#define G64_SMEM ((64*GA*2 + 32*GB*2) * 4)     // 53248 bytes

__device__ __forceinline__
void gemm64_body(const float* __restrict__ A, const float* __restrict__ W,
                 const float* __restrict__ bias,
                 float* __restrict__ Ch, float* __restrict__ Cl, float scale,
                 int M, int K, int N)
{
    extern __shared__ float gsm[];
    float* Ash = gsm;                     // [64][GA]
    float* Asl = Ash + 64 * GA;
    float* Bsh = Asl + 64 * GA;           // [32][GB]
    float* Bsl = Bsh + 32 * GB;

    const int t    = threadIdx.x;
    const int m0   = blockIdx.y * 64;
    const int n0   = blockIdx.x * 128;
    const int w    = t >> 5;
    const int lane = t & 31;
    const int wm   = w >> 2;              // 0..1
    const int wn   = w & 3;               // 0..3
    const int grp  = lane >> 2;
    const int tg   = lane & 3;

    float acc[2][4][4];
#pragma unroll
    for (int i = 0; i < 2; ++i)
#pragma unroll
        for (int j = 0; j < 4; ++j)
#pragma unroll
            for (int c = 0; c < 4; ++c) acc[i][j][c] = 0.f;

    const float* Aptr = A + (size_t)m0 * K;
    const float* Wptr = W + n0;

    for (int k0 = 0; k0 < K; k0 += 32) {
#pragma unroll
        for (int i = 0; i < 2; ++i) {
            int idx = t + i * 256;               // 0..511
            int row = idx >> 3;                  // 0..63
            int c4  = (idx & 7) * 4;
            float4 v = *(const float4*)(Aptr + (size_t)row * K + k0 + c4);
            float h0, l0, h1, l1, h2, l2, h3, l3;
            split2(v.x, h0, l0); split2(v.y, h1, l1);
            split2(v.z, h2, l2); split2(v.w, h3, l3);
            *(float4*)&Ash[row * GA + c4] = make_float4(h0, h1, h2, h3);
            *(float4*)&Asl[row * GA + c4] = make_float4(l0, l1, l2, l3);
        }
#pragma unroll
        for (int i = 0; i < 4; ++i) {
            int idx = t + i * 256;
            int row = idx >> 5;                  // 0..31
            int c4  = (idx & 31) * 4;
            float4 v = *(const float4*)(Wptr + (size_t)(k0 + row) * N + c4);
            float h0, l0, h1, l1, h2, l2, h3, l3;
            split2(v.x, h0, l0); split2(v.y, h1, l1);
            split2(v.z, h2, l2); split2(v.w, h3, l3);
            *(float4*)&Bsh[row * GB + c4] = make_float4(h0, h1, h2, h3);
            *(float4*)&Bsl[row * GB + c4] = make_float4(l0, l1, l2, l3);
        }
        __syncthreads();

#pragma unroll
        for (int ks = 0; ks < 4; ++ks) {
            const int ka = ks * 8 + tg;
            unsigned bh[4][2], bl[4][2];
#pragma unroll
            for (int nt = 0; nt < 4; ++nt) {
                int c = wn * 32 + nt * 8 + grp;
                bh[nt][0] = fu(Bsh[ka * GB + c]);
                bh[nt][1] = fu(Bsh[(ka + 4) * GB + c]);
                bl[nt][0] = fu(Bsl[ka * GB + c]);
                bl[nt][1] = fu(Bsl[(ka + 4) * GB + c]);
            }
#pragma unroll
            for (int mt = 0; mt < 2; ++mt) {
                int r = wm * 32 + mt * 16 + grp;
                unsigned ah0 = fu(Ash[r * GA + ka]);
                unsigned ah1 = fu(Ash[(r + 8) * GA + ka]);
                unsigned ah2 = fu(Ash[r * GA + ka + 4]);
                unsigned ah3 = fu(Ash[(r + 8) * GA + ka + 4]);
                unsigned al0 = fu(Asl[r * GA + ka]);
                unsigned al1 = fu(Asl[(r + 8) * GA + ka]);
                unsigned al2 = fu(Asl[r * GA + ka + 4]);
                unsigned al3 = fu(Asl[(r + 8) * GA + ka + 4]);
#pragma unroll
                for (int nt = 0; nt < 4; ++nt) {
                    mma_tf32(acc[mt][nt], ah0, ah1, ah2, ah3, bh[nt][0], bh[nt][1]);
                    mma_tf32(acc[mt][nt], ah0, ah1, ah2, ah3, bl[nt][0], bl[nt][1]);
                    mma_tf32(acc[mt][nt], al0, al1, al2, al3, bh[nt][0], bh[nt][1]);
                }
            }
        }
        __syncthreads();
    }

    if (Cl == nullptr) {
#pragma unroll
        for (int nt = 0; nt < 4; ++nt) {
            const int c = n0 + wn * 32 + nt * 8 + 2 * tg;
            float2 bv = *(const float2*)&bias[c];
#pragma unroll
            for (int mt = 0; mt < 2; ++mt) {
                int r = m0 + wm * 32 + mt * 16 + grp;
                float2 r0 = make_float2(acc[mt][nt][0] + bv.x, acc[mt][nt][1] + bv.y);
                float2 r1 = make_float2(acc[mt][nt][2] + bv.x, acc[mt][nt][3] + bv.y);
                *(float2*)&Ch[(size_t)r * N + c]       = r0;
                *(float2*)&Ch[(size_t)(r + 8) * N + c] = r1;
            }
        }
    } else {
#pragma unroll
        for (int nt = 0; nt < 4; ++nt) {
            const int c = n0 + wn * 32 + nt * 8 + 2 * tg;
            float2 bv = *(const float2*)&bias[c];
#pragma unroll
            for (int mt = 0; mt < 2; ++mt) {
                int r = m0 + wm * 32 + mt * 16 + grp;
                float v00 = (acc[mt][nt][0] + bv.x) * scale;
                float v01 = (acc[mt][nt][1] + bv.y) * scale;
                float v10 = (acc[mt][nt][2] + bv.x) * scale;
                float v11 = (acc[mt][nt][3] + bv.y) * scale;
                float h00, l00, h01, l01, h10, l10, h11, l11;
                split2(v00, h00, l00); split2(v01, h01, l01);
                split2(v10, h10, l10); split2(v11, h11, l11);
                *(float2*)&Ch[(size_t)r * N + c]       = make_float2(h00, h01);
                *(float2*)&Ch[(size_t)(r + 8) * N + c] = make_float2(h10, h11);
                *(float2*)&Cl[(size_t)r * N + c]       = make_float2(l00, l01);
                *(float2*)&Cl[(size_t)(r + 8) * N + c] = make_float2(l10, l11);
            }
        }
    }
}

// ---- weight combination: grid (4, 4, 12), 128-tile ----
__global__ __launch_bounds__(256, 2)
void combine_w(const float* __restrict__ emb_w,
               const float* __restrict__ Wq, const float* __restrict__ Wk,
               const float* __restrict__ Wv, const float* __restrict__ Wo)
{
    const int z = blockIdx.z;
    if (z < 9) {
        const int l = z / 3 + 1, j = z % 3;
        const float* Wsel = (j == 0 ? Wq : j == 1 ? Wk : Wv) + (size_t)l * E_ * E_;
        gemm_body(Wo + (size_t)(l - 1) * E_ * E_, Wsel, g_zero,
                  g_cw + (size_t)z * E_ * E_, nullptr, 1.f, E_, E_, E_);
    } else {
        if (blockIdx.y != 0) return;
        const int j = z - 9;
        const float* Wsel = (j == 0 ? Wq : j == 1 ? Wk : Wv);
        gemm_body(emb_w, Wsel, g_zero,
                  g_cw0 + (size_t)j * FIN * E_, nullptr, 1.f, FIN, E_, E_);
    }
}

__global__ void combine_b(const float* __restrict__ emb_b,
                          const float* __restrict__ Wq, const float* __restrict__ Wk,
                          const float* __restrict__ Wv,
                          const float* __restrict__ bq, const float* __restrict__ bk,
                          const float* __restrict__ bv, const float* __restrict__ bo)
{
    const int l = blockIdx.x / 3, j = blockIdx.x % 3;
    const int t = threadIdx.x;
    const float* W = (j == 0 ? Wq : j == 1 ? Wk : Wv) + (size_t)l * E_ * E_;
    const float* badd = (j == 0 ? bq : j == 1 ? bk : bv) + (size_t)l * E_;
    float s = 0.f;
    if (l == 0) {
        for (int k = 0; k < FIN; ++k) s += emb_b[k] * W[(size_t)k * E_ + t];
    } else {
        const float* bvp = bo + (size_t)(l - 1) * E_;
        for (int k = 0; k < E_; ++k) s += bvp[k] * W[(size_t)k * E_ + t];
    }
    g_cb[blockIdx.x * E_ + t] = s + badd[t];
}

__global__ void fc_fold(const float* __restrict__ Wo, const float* __restrict__ fc_w,
                        const float* __restrict__ fc_b, const float* __restrict__ bo)
{
    const int t = blockIdx.x * 1024 + threadIdx.x;
    const float* Wo3 = Wo + (size_t)3 * E_ * E_;
    if (t < E_ * NCLS) {
        const int i = t / NCLS, c = t % NCLS;
        float s = 0.f;
        for (int k = 0; k < E_; ++k)
            s += Wo3[(size_t)i * E_ + k] * fc_w[k * NCLS + c];
        g_fcw[t] = s;
    }
    if (t < NCLS) {
        const float* bo3 = bo + (size_t)3 * E_;
        float s = fc_b[t];
        for (int k = 0; k < E_; ++k)
            s += bo3[k] * fc_w[k * NCLS + t];
        g_fcb[t] = s;
    }
}

// QKV projection, 64-row tiles: grid (4, 128, 3)
__global__ __launch_bounds__(256, 2)
void gemm_qkv64(const float* __restrict__ A,
                const float* __restrict__ Wq_, const float* __restrict__ Wk_,
                const float* __restrict__ Wv_,
                const float* __restrict__ bq_, const float* __restrict__ bk_,
                const float* __restrict__ bv_, int K)
{
    if (blockIdx.z == 0)
        gemm64_body(A, Wq_, bq_, g_qh, g_ql, 0.125f, B_ * S_, K, E_);
    else if (blockIdx.z == 1)
        gemm64_body(A, Wk_, bk_, g_k, nullptr, 1.f, B_ * S_, K, E_);
    else
        gemm64_body(A, Wv_, bv_, g_v, nullptr, 1.f, B_ * S_, K, E_);
}

// ======================================================================
// Sparse attention (R11 structure + fragment-major Q planes).
//  phase1: S = Q K^T; Q A-frags = 1 LDS.128 each (frag-major smem);
//          K raw in smem; acc[2][2] = 4 indep chains; St[q][key] row-major
//  phase2: exact top-k (early-exit) + softmax
//  phase3: O = P V, 256-key chunks, acc[2][2]
// ======================================================================
#define SP   1028              // St row stride (== 4 mod 32)
#define KPR  68                // K raw stride (B-frags cf)
#define VPR  72                // V raw stride (B-frags cf)

#define ST_F (32 * SP)         // 32896 floats
#define QF_F 2048              // per plane: 16 frags x 32 lanes x 4
#define KV_F (256 * VPR)       // 18432 floats
#define ATTN_SMEM ((ST_F + 2 * QF_F + KV_F) * 4)   // 221696 bytes

__global__ __launch_bounds__(512, 1)
void attn_kernel()
{
    extern __shared__ float sm[];
    float* St  = sm;                    // [32][SP]   scores then P (fp32)
    float* QFh = sm + ST_F;             // fragment-major Q hi (prescaled)
    float* QFl = QFh + QF_F;            // fragment-major Q lo
    float* KV  = QFl + QF_F;            // K raw [256][68] / V raw [256][72] / red

    const int t    = threadIdx.x;
    const int w    = t >> 5;
    const int lane = t & 31;
    const int grp  = lane >> 2;
    const int tg   = lane & 3;

    const int gid = blockIdx.x;
    const int qt  = gid & 31;
    const int hh  = (gid >> 5) & 7;
    const int b   = gid >> 8;

    const size_t qoff = ((size_t)(b * S_ + qt * QT)) * E_ + hh * D_;
    const size_t koff = ((size_t)b * S_) * E_ + hh * D_;

    const float* Qh = g_qh + qoff;
    const float* Ql = g_ql + qoff;
    const float* Kg = g_k + koff;
    const float* Vg = g_v + koff;
    float*       Og = g_o + qoff;

    // ---- phase 0: Q planes -> fragment-major smem ----
    // frag = mt*8+ks (16 frags); vec = [Q(r,ka),Q(r+8,ka),Q(r,ka+4),Q(r+8,ka+4)]
    {
        const int frag = t >> 5;            // 0..15
        const int ln   = t & 31;
        const int mt = frag >> 3, ks = frag & 7;
        const int g2 = ln >> 2,  t2 = ln & 3;
        const int r  = mt * 16 + g2;
        const int ka = ks * 8 + t2;
        const float* qh = Qh + (size_t)r * E_ + ka;
        const float* ql = Ql + (size_t)r * E_ + ka;
        *(float4*)&QFh[t * 4] =
            make_float4(qh[0], qh[8 * E_], qh[4], qh[8 * E_ + 4]);
        *(float4*)&QFl[t * 4] =
            make_float4(ql[0], ql[8 * E_], ql[4], ql[8 * E_ + 4]);
    }

    // ---- phase 1: scores S[q][key]; 256-key chunks; warp owns 16 keys ----
    {
        float* Ksm = KV;

        for (int kc = 0; kc < S_; kc += 256) {
#pragma unroll
            for (int i = 0; i < 8; ++i) {
                int idx = t + i * 512;
                int row = idx >> 4;
                int c4  = (idx & 15) * 4;
                *(float4*)&Ksm[row * KPR + c4] =
                    *(const float4*)(Kg + (size_t)(kc + row) * E_ + c4);
            }
            __syncthreads();                // also covers phase-0 QF writes

            float acc[2][2][4];
#pragma unroll
            for (int mt = 0; mt < 2; ++mt)
#pragma unroll
                for (int nt = 0; nt < 2; ++nt)
#pragma unroll
                    for (int c = 0; c < 4; ++c) acc[mt][nt][c] = 0.f;

#pragma unroll
            for (int ks = 0; ks < 8; ++ks) {
                const int ka = ks * 8 + tg;
                unsigned ah[2][4], al[2][4];
#pragma unroll
                for (int mt = 0; mt < 2; ++mt) {
                    const int frag = mt * 8 + ks;
                    float4 h4 = *(const float4*)&QFh[(frag * 32 + lane) * 4];
                    float4 l4 = *(const float4*)&QFl[(frag * 32 + lane) * 4];
                    ah[mt][0] = fu(h4.x); ah[mt][1] = fu(h4.y);
                    ah[mt][2] = fu(h4.z); ah[mt][3] = fu(h4.w);
                    al[mt][0] = fu(l4.x); al[mt][1] = fu(l4.y);
                    al[mt][2] = fu(l4.z); al[mt][3] = fu(l4.w);
                }
                unsigned bh[2][2], bl[2][2];
#pragma unroll
                for (int nt = 0; nt < 2; ++nt) {
                    const int key = w * 16 + nt * 8 + grp;
                    float y0 = Ksm[key * KPR + ka];
                    float y1 = Ksm[key * KPR + ka + 4];
                    float h0, l0, h1, l1;
                    split2(y0, h0, l0); split2(y1, h1, l1);
                    bh[nt][0] = fu(h0); bh[nt][1] = fu(h1);
                    bl[nt][0] = fu(l0); bl[nt][1] = fu(l1);
                }
#pragma unroll
                for (int mt = 0; mt < 2; ++mt)
#pragma unroll
                    for (int nt = 0; nt < 2; ++nt) {
                        mma_tf32(acc[mt][nt], ah[mt][0], ah[mt][1], ah[mt][2], ah[mt][3],
                                 bh[nt][0], bh[nt][1]);
                        mma_tf32(acc[mt][nt], ah[mt][0], ah[mt][1], ah[mt][2], ah[mt][3],
                                 bl[nt][0], bl[nt][1]);
                        mma_tf32(acc[mt][nt], al[mt][0], al[mt][1], al[mt][2], al[mt][3],
                                 bh[nt][0], bh[nt][1]);
                    }
            }
            const int keyb = kc + w * 16;
#pragma unroll
            for (int mt = 0; mt < 2; ++mt)
#pragma unroll
                for (int nt = 0; nt < 2; ++nt) {
                    const int q = mt * 16 + grp;
                    const int k = keyb + nt * 8 + 2 * tg;
                    *(float2*)&St[(size_t)q * SP + k] =
                        make_float2(acc[mt][nt][0], acc[mt][nt][1]);
                    *(float2*)&St[(size_t)(q + 8) * SP + k] =
                        make_float2(acc[mt][nt][2], acc[mt][nt][3]);
                }
            __syncthreads();
        }
    }

    // ---- phase 2: exact top-k + softmax; warp w owns queries 2w, 2w+1 ----
#pragma unroll
    for (int qq = 0; qq < 2; ++qq) {
        const int qi = w * 2 + qq;
        float* row = St + (size_t)qi * SP;

        unsigned u[32];
        unsigned umax = 0u, umin = 0xFFFFFFFFu;
#pragma unroll
        for (int i = 0; i < 32; ++i) {
            u[i] = fmap(row[lane + 32 * i]);
            umax = max(umax, u[i]);
            umin = min(umin, u[i]);
        }
        umax = __reduce_max_sync(0xFFFFFFFFu, umax);
        umin = __reduce_min_sync(0xFFFFFFFFu, umin);

        unsigned lo = umin, hi = umax, thr;
        for (;;) {
            if (lo >= hi) { thr = lo; break; }
            unsigned mid = lo + ((hi - lo + 1) >> 1);
            unsigned c = 0;
#pragma unroll
            for (int i = 0; i < 32; ++i) c += (u[i] >= mid);
            c = __reduce_add_sync(0xFFFFFFFFu, c);
            if (c == KTOP) { thr = mid; break; }   // kept set identical to exact
            if (c > KTOP) lo = mid; else hi = mid - 1;
        }
        const float mf = unfmap(umax);

        float sum = 0.f;
#pragma unroll
        for (int i = 0; i < 32; ++i) {
            float ev = 0.f;
            if (u[i] >= thr) ev = __expf(unfmap(u[i]) - mf);
            u[i] = __float_as_uint(ev);
            sum += ev;
        }
#pragma unroll
        for (int off = 16; off > 0; off >>= 1)
            sum += __shfl_xor_sync(0xFFFFFFFFu, sum, off);
        const float inv = 1.f / sum;

#pragma unroll
        for (int i = 0; i < 32; ++i)
            row[lane + 32 * i] = __uint_as_float(u[i]) * inv;
    }
    __syncthreads();

    // ---- phase 3: O = P V ; 256-key chunks; warp = (kg 0..3, wn 0..3) ----
    {
        float* Vsm = KV;
        const int kg = w >> 2;
        const int wn = w & 3;

        float acc[2][2][4];
#pragma unroll
        for (int mt = 0; mt < 2; ++mt)
#pragma unroll
            for (int nt = 0; nt < 2; ++nt)
#pragma unroll
                for (int c = 0; c < 4; ++c) acc[mt][nt][c] = 0.f;

        for (int kc = 0; kc < S_; kc += 256) {
#pragma unroll
            for (int i = 0; i < 8; ++i) {
                int idx = t + i * 512;
                int row = idx >> 4;
                int c4  = (idx & 15) * 4;
                *(float4*)&Vsm[row * VPR + c4] =
                    *(const float4*)(Vg + (size_t)(kc + row) * E_ + c4);
            }
            __syncthreads();

#pragma unroll
            for (int ks = 0; ks < 8; ++ks) {
                const int kl = kg * 64 + ks * 8;
                const int k0 = kc + kl;

                unsigned bh[2][2], bl[2][2];
#pragma unroll
                for (int nt = 0; nt < 2; ++nt) {
                    const int col = wn * 16 + nt * 8 + grp;
                    float y0 = Vsm[(kl + tg) * VPR + col];
                    float y1 = Vsm[(kl + tg + 4) * VPR + col];
                    float h0, l0, h1, l1;
                    split2(y0, h0, l0); split2(y1, h1, l1);
                    bh[nt][0] = fu(h0); bh[nt][1] = fu(h1);
                    bl[nt][0] = fu(l0); bl[nt][1] = fu(l1);
                }
#pragma unroll
                for (int mt = 0; mt < 2; ++mt) {
                    float p0 = St[(mt * 16 + grp) * SP + k0 + tg];
                    float p1 = St[(mt * 16 + grp + 8) * SP + k0 + tg];
                    float p2 = St[(mt * 16 + grp) * SP + k0 + tg + 4];
                    float p3 = St[(mt * 16 + grp + 8) * SP + k0 + tg + 4];
                    float h0, l0, h1, l1, h2, l2, h3, l3;
                    split2(p0, h0, l0); split2(p1, h1, l1);
                    split2(p2, h2, l2); split2(p3, h3, l3);
                    unsigned ah0 = fu(h0), ah1 = fu(h1), ah2 = fu(h2), ah3 = fu(h3);
                    unsigned al0 = fu(l0), al1 = fu(l1), al2 = fu(l2), al3 = fu(l3);
#pragma unroll
                    for (int nt = 0; nt < 2; ++nt) {
                        mma_tf32(acc[mt][nt], ah0, ah1, ah2, ah3, bh[nt][0], bh[nt][1]);
                        mma_tf32(acc[mt][nt], ah0, ah1, ah2, ah3, bl[nt][0], bl[nt][1]);
                        mma_tf32(acc[mt][nt], al0, al1, al2, al3, bh[nt][0], bh[nt][1]);
                    }
                }
            }
            __syncthreads();
        }

        float* red = KV;                    // [4][32][68]
#pragma unroll
        for (int mt = 0; mt < 2; ++mt)
#pragma unroll
            for (int nt = 0; nt < 2; ++nt) {
                const int q = mt * 16 + grp;
                const int d = wn * 16 + nt * 8 + 2 * tg;
                *(float2*)&red[kg * 2176 + q * 68 + d] =
                    make_float2(acc[mt][nt][0], acc[mt][nt][1]);
                *(float2*)&red[kg * 2176 + (q + 8) * 68 + d] =
                    make_float2(acc[mt][nt][2], acc[mt][nt][3]);
            }
        __syncthreads();

#pragma unroll
        for (int kk = 0; kk < 4; ++kk) {
            int m  = t + kk * 512;
            int qi = m >> 6, dd = m & 63;
            float s = red[0 * 2176 + qi * 68 + dd] + red[1 * 2176 + qi * 68 + dd]
                    + red[2 * 2176 + qi * 68 + dd] + red[3 * 2176 + qi * 68 + dd];
            Og[(size_t)qi * E_ + dd] = s;
        }
    }
}

// ======================================================================
// mean pool + final FC
// ======================================================================
__global__ void meanpool_k(const float* __restrict__ h, float* __restrict__ pool)
{
    __shared__ float red[512];
    const int b = blockIdx.y;
    const int e = blockIdx.x * 128 + (threadIdx.x & 127);
    const int slice = threadIdx.x >> 7;
    const float* base = h + (size_t)b * S_ * E_ + e;
    float s = 0.f;
#pragma unroll 8
    for (int i = 0; i < 256; ++i)
        s += base[(size_t)(slice * 256 + i) * E_];
    red[threadIdx.x] = s;
    __syncthreads();
    if (slice == 0) {
        float tot = red[threadIdx.x] + red[threadIdx.x + 128] +
                    red[threadIdx.x + 256] + red[threadIdx.x + 384];
        pool[b * E_ + e] = tot * (1.f / (float)S_);
    }
}

__global__ void fc_k(const float* __restrict__ pool, const float* __restrict__ w,
                     const float* __restrict__ bias, float* __restrict__ out)
{
    int t = threadIdx.x;
    if (t >= B_ * NCLS) return;
    int b = t / NCLS, c = t % NCLS;
    float s = bias[c];
    const float* p = pool + b * E_;
#pragma unroll 8
    for (int k = 0; k < E_; ++k)
        s += p[k] * w[k * NCLS + c];
    out[t] = s;
}

// ======================================================================
// launch
// ======================================================================
extern "C" void kernel_launch(void* const* d_in, const int* in_sizes, int n_in,
                              void* d_out, int out_size)
{
    (void)in_sizes; (void)n_in; (void)out_size;

    const float* x     = (const float*)d_in[0];
    const float* emb_w = (const float*)d_in[1];
    const float* emb_b = (const float*)d_in[2];
    const float* Wq    = (const float*)d_in[3];
    const float* Wk    = (const float*)d_in[4];
    const float* Wv    = (const float*)d_in[5];
    const float* Wo    = (const float*)d_in[6];
    const float* bq    = (const float*)d_in[7];
    const float* bk    = (const float*)d_in[8];
    const float* bv    = (const float*)d_in[9];
    const float* bo    = (const float*)d_in[10];
    const float* fc_w  = (const float*)d_in[11];
    const float* fc_b  = (const float*)d_in[12];
    float* out = (float*)d_out;

    float *o, *pool, *cw0, *cw, *cb, *fcw, *fcb;
    cudaGetSymbolAddress((void**)&o,    g_o);
    cudaGetSymbolAddress((void**)&pool, g_pool);
    cudaGetSymbolAddress((void**)&cw0,  g_cw0);
    cudaGetSymbolAddress((void**)&cw,   g_cw);
    cudaGetSymbolAddress((void**)&cb,   g_cb);
    cudaGetSymbolAddress((void**)&fcw,  g_fcw);
    cudaGetSymbolAddress((void**)&fcb,  g_fcb);

    cudaFuncSetAttribute(attn_kernel, cudaFuncAttributeMaxDynamicSharedMemorySize, ATTN_SMEM);
    cudaFuncSetAttribute(gemm_qkv64,  cudaFuncAttributeMaxDynamicSharedMemorySize, G64_SMEM);
    cudaFuncSetAttribute(combine_w,   cudaFuncAttributeMaxDynamicSharedMemorySize, GEMM_SMEM);

    const int M = B_ * S_;                          // 8192
    dim3 qkvgrid(E_ / 128, M / 64, 3);              // (4, 128, 3)
    const int attn_grid = B_ * H_ * (S_ / QT);      // 2048

    // ---- weight/bias folding ----
    combine_w<<<dim3(4, 4, 12), 256, GEMM_SMEM>>>(emb_w, Wq, Wk, Wv, Wo);
    combine_b<<<12, E_>>>(emb_b, Wq, Wk, Wv, bq, bk, bv, bo);
    fc_fold<<<5, 1024>>>(Wo, fc_w, fc_b, bo);

    // ---- layer 0: QKV directly from x (K = FIN = 128) ----
    gemm_qkv64<<<qkvgrid, 256, G64_SMEM>>>(
        x, cw0, cw0 + FIN * E_, cw0 + 2 * FIN * E_,
        cb, cb + E_, cb + 2 * E_, FIN);
    attn_kernel<<<attn_grid, 512, ATTN_SMEM>>>();

    // ---- layers 1..3: QKV from o with folded Wo (K = 512) ----
    for (int l = 1; l < L_; ++l) {
        const size_t wb = (size_t)(l - 1) * 3 * E_ * E_;
        const size_t bb = (size_t)l * 3 * E_;
        gemm_qkv64<<<qkvgrid, 256, G64_SMEM>>>(
            o, cw + wb, cw + wb + (size_t)E_ * E_, cw + wb + (size_t)2 * E_ * E_,
            cb + bb, cb + bb + E_, cb + bb + 2 * E_, E_);
        attn_kernel<<<attn_grid, 512, ATTN_SMEM>>>();
    }

    // ---- pool over o3, FC with folded weights ----
    meanpool_k<<<dim3(E_ / 128, B_), 512>>>(o, pool);
    fc_k<<<1, 128>>>(pool, fcw, fcb, out);
}

// round 14
// speedup vs baseline: 1.0880x; 1.0880x over previous
#include <cuda_runtime.h>
#include <math.h>

// ---------------- problem constants ----------------
#define B_   8
#define S_   1024
#define E_   512
#define H_   8
#define D_   64
#define L_   4
#define KTOP 256
#define FIN  128
#define NCLS 10
#define QT   32

// ---------------- device scratch ----------------
__device__ float g_o [(size_t)B_ * S_ * E_];
__device__ float g_qh[(size_t)B_ * S_ * E_];
__device__ float g_ql[(size_t)B_ * S_ * E_];
__device__ float g_k [(size_t)B_ * S_ * E_];
__device__ float g_v [(size_t)B_ * S_ * E_];
__device__ float g_pool[B_ * E_];
__device__ float g_zero[E_];                       // zero-initialized
// combined weights/biases
__device__ float g_cw0[3 * FIN * E_];              // layer0: emb_w @ W{q,k,v}0
__device__ float g_cw [9 * E_ * E_];               // layers1-3: Wo_{l-1} @ W{q,k,v}_l
__device__ float g_cb [12 * E_];                   // combined biases [l*3+j]
__device__ float g_fcw[E_ * NCLS];                 // Wo3 @ fc_w
__device__ float g_fcb[NCLS];                      // bo3 @ fc_w + fc_b

// ---------------- helpers ----------------
__device__ __forceinline__ float tf32f(float x) {
    unsigned u;
    asm("cvt.rna.tf32.f32 %0, %1;" : "=r"(u) : "f"(x));
    return __uint_as_float(u);
}
__device__ __forceinline__ void mma_tf32(float c[4],
    unsigned a0, unsigned a1, unsigned a2, unsigned a3,
    unsigned b0, unsigned b1)
{
    asm volatile(
        "mma.sync.aligned.m16n8k8.row.col.f32.tf32.tf32.f32 "
        "{%0,%1,%2,%3},{%4,%5,%6,%7},{%8,%9},{%0,%1,%2,%3};"
        : "+f"(c[0]), "+f"(c[1]), "+f"(c[2]), "+f"(c[3])
        : "r"(a0), "r"(a1), "r"(a2), "r"(a3), "r"(b0), "r"(b1));
}
__device__ __forceinline__ unsigned fu(float x) { return __float_as_uint(x); }

__device__ __forceinline__ unsigned fmap(float x) {
    unsigned u = __float_as_uint(x);
    return (u & 0x80000000u) ? ~u : (u | 0x80000000u);
}
__device__ __forceinline__ float unfmap(unsigned u) {
    return (u & 0x80000000u) ? __uint_as_float(u & 0x7FFFFFFFu)
                             : __uint_as_float(~u);
}
__device__ __forceinline__ void split2(float x, float& h, float& l) {
    h = tf32f(x);
    l = tf32f(x - h);
}

// ======================================================================
// split-tf32 GEMM (R4/R9 form: split at smem-store, synchronous loop).
// C = A[M,K] @ W[K,N] + bias. 128x128 tile, BK=32, 256 thr = 8 warps.
// Optional split-output epilogue: (acc+bias)*scale -> hi/lo planes.
// ======================================================================
#define GA 36
#define GB 136
#define GEMM_SMEM ((128*GA*2 + 32*GB*2) * 4)   // 71680 bytes

__device__ __forceinline__
void gemm_body(const float* __restrict__ A, const float* __restrict__ W,
               const float* __restrict__ bias,
               float* __restrict__ Ch, float* __restrict__ Cl, float scale,
               int M, int K, int N)
{
    extern __shared__ float gsm[];
    float* Ash = gsm;
    float* Asl = Ash + 128 * GA;
    float* Bsh = Asl + 128 * GA;
    float* Bsl = Bsh + 32 * GB;

    const int t    = threadIdx.x;
    const int m0   = blockIdx.y * 128;
    const int n0   = blockIdx.x * 128;
    const int w    = t >> 5;
    const int lane = t & 31;
    const int wm   = w >> 2;
    const int wn   = w & 3;
    const int grp  = lane >> 2;
    const int tg   = lane & 3;

    float acc[4][4][4];
#pragma unroll
    for (int i = 0; i < 4; ++i)
#pragma unroll
        for (int j = 0; j < 4; ++j)
#pragma unroll
            for (int c = 0; c < 4; ++c) acc[i][j][c] = 0.f;

    const float* Aptr = A + (size_t)m0 * K;
    const float* Wptr = W + n0;

    for (int k0 = 0; k0 < K; k0 += 32) {
#pragma unroll
        for (int i = 0; i < 4; ++i) {
            int idx = t + i * 256;
            int row = idx >> 3;
            int c4  = (idx & 7) * 4;
            float4 v = *(const float4*)(Aptr + (size_t)row * K + k0 + c4);
            float h0, l0, h1, l1, h2, l2, h3, l3;
            split2(v.x, h0, l0); split2(v.y, h1, l1);
            split2(v.z, h2, l2); split2(v.w, h3, l3);
            *(float4*)&Ash[row * GA + c4] = make_float4(h0, h1, h2, h3);
            *(float4*)&Asl[row * GA + c4] = make_float4(l0, l1, l2, l3);
        }
#pragma unroll
        for (int i = 0; i < 4; ++i) {
            int idx = t + i * 256;
            int row = idx >> 5;
            int c4  = (idx & 31) * 4;
            float4 v = *(const float4*)(Wptr + (size_t)(k0 + row) * N + c4);
            float h0, l0, h1, l1, h2, l2, h3, l3;
            split2(v.x, h0, l0); split2(v.y, h1, l1);
            split2(v.z, h2, l2); split2(v.w, h3, l3);
            *(float4*)&Bsh[row * GB + c4] = make_float4(h0, h1, h2, h3);
            *(float4*)&Bsl[row * GB + c4] = make_float4(l0, l1, l2, l3);
        }
        __syncthreads();

#pragma unroll
        for (int ks = 0; ks < 4; ++ks) {
            const int ka = ks * 8 + tg;
            unsigned bh[4][2], bl[4][2];
#pragma unroll
            for (int nt = 0; nt < 4; ++nt) {
                int c = wn * 32 + nt * 8 + grp;
                bh[nt][0] = fu(Bsh[ka * GB + c]);
                bh[nt][1] = fu(Bsh[(ka + 4) * GB + c]);
                bl[nt][0] = fu(Bsl[ka * GB + c]);
                bl[nt][1] = fu(Bsl[(ka + 4) * GB + c]);
            }
#pragma unroll
            for (int mt = 0; mt < 4; ++mt) {
                int r = wm * 64 + mt * 16 + grp;
                unsigned ah0 = fu(Ash[r * GA + ka]);
                unsigned ah1 = fu(Ash[(r + 8) * GA + ka]);
                unsigned ah2 = fu(Ash[r * GA + ka + 4]);
                unsigned ah3 = fu(Ash[(r + 8) * GA + ka + 4]);
                unsigned al0 = fu(Asl[r * GA + ka]);
                unsigned al1 = fu(Asl[(r + 8) * GA + ka]);
                unsigned al2 = fu(Asl[r * GA + ka + 4]);
                unsigned al3 = fu(Asl[(r + 8) * GA + ka + 4]);
#pragma unroll
                for (int nt = 0; nt < 4; ++nt) {
                    mma_tf32(acc[mt][nt], ah0, ah1, ah2, ah3, bh[nt][0], bh[nt][1]);
                    mma_tf32(acc[mt][nt], ah0, ah1, ah2, ah3, bl[nt][0], bl[nt][1]);
                    mma_tf32(acc[mt][nt], al0, al1, al2, al3, bh[nt][0], bh[nt][1]);
                }
            }
        }
        __syncthreads();
    }

    if (Cl == nullptr) {
#pragma unroll
        for (int nt = 0; nt < 4; ++nt) {
            const int c = n0 + wn * 32 + nt * 8 + 2 * tg;
            float2 bv = *(const float2*)&bias[c];
#pragma unroll
            for (int mt = 0; mt < 4; ++mt) {
                int r = m0 + wm * 64 + mt * 16 + grp;
                float2 r0 = make_float2(acc[mt][nt][0] + bv.x, acc[mt][nt][1] + bv.y);
                float2 r1 = make_float2(acc[mt][nt][2] + bv.x, acc[mt][nt][3] + bv.y);
                *(float2*)&Ch[(size_t)r * N + c]       = r0;
                *(float2*)&Ch[(size_t)(r + 8) * N + c] = r1;
            }
        }
    } else {
#pragma unroll
        for (int nt = 0; nt < 4; ++nt) {
            const int c = n0 + wn * 32 + nt * 8 + 2 * tg;
            float2 bv = *(const float2*)&bias[c];
#pragma unroll
            for (int mt = 0; mt < 4; ++mt) {
                int r = m0 + wm * 64 + mt * 16 + grp;
                float v00 = (acc[mt][nt][0] + bv.x) * scale;
                float v01 = (acc[mt][nt][1] + bv.y) * scale;
                float v10 = (acc[mt][nt][2] + bv.x) * scale;
                float v11 = (acc[mt][nt][3] + bv.y) * scale;
                float h00, l00, h01, l01, h10, l10, h11, l11;
                split2(v00, h00, l00); split2(v01, h01, l01);
                split2(v10, h10, l10); split2(v11, h11, l11);
                *(float2*)&Ch[(size_t)r * N + c]       = make_float2(h00, h01);
                *(float2*)&Ch[(size_t)(r + 8) * N + c] = make_float2(h10, h11);
                *(float2*)&Cl[(size_t)r * N + c]       = make_float2(l00, l01);
                *(float2*)&Cl[(size_t)(r + 8) * N + c] = make_float2(l10, l11);
            }
        }
    }
}

// ---- weight combination: grid (4, 4, 12) ----
__global__ __launch_bounds__(256, 2)
void combine_w(const float* __restrict__ emb_w,
               const float* __restrict__ Wq, const float* __restrict__ Wk,
               const float* __restrict__ Wv, const float* __restrict__ Wo)
{
    const int z = blockIdx.z;
    if (z < 9) {
        const int l = z / 3 + 1, j = z % 3;
        const float* Wsel = (j == 0 ? Wq : j == 1 ? Wk : Wv) + (size_t)l * E_ * E_;
        gemm_body(Wo + (size_t)(l - 1) * E_ * E_, Wsel, g_zero,
                  g_cw + (size_t)z * E_ * E_, nullptr, 1.f, E_, E_, E_);
    } else {
        if (blockIdx.y != 0) return;
        const int j = z - 9;
        const float* Wsel = (j == 0 ? Wq : j == 1 ? Wk : Wv);
        gemm_body(emb_w, Wsel, g_zero,
                  g_cw0 + (size_t)j * FIN * E_, nullptr, 1.f, FIN, E_, E_);
    }
}

__global__ void combine_b(const float* __restrict__ emb_b,
                          const float* __restrict__ Wq, const float* __restrict__ Wk,
                          const float* __restrict__ Wv,
                          const float* __restrict__ bq, const float* __restrict__ bk,
                          const float* __restrict__ bv, const float* __restrict__ bo)
{
    const int l = blockIdx.x / 3, j = blockIdx.x % 3;
    const int t = threadIdx.x;
    const float* W = (j == 0 ? Wq : j == 1 ? Wk : Wv) + (size_t)l * E_ * E_;
    const float* badd = (j == 0 ? bq : j == 1 ? bk : bv) + (size_t)l * E_;
    float s = 0.f;
    if (l == 0) {
        for (int k = 0; k < FIN; ++k) s += emb_b[k] * W[(size_t)k * E_ + t];
    } else {
        const float* bvp = bo + (size_t)(l - 1) * E_;
        for (int k = 0; k < E_; ++k) s += bvp[k] * W[(size_t)k * E_ + t];
    }
    g_cb[blockIdx.x * E_ + t] = s + badd[t];
}

__global__ void fc_fold(const float* __restrict__ Wo, const float* __restrict__ fc_w,
                        const float* __restrict__ fc_b, const float* __restrict__ bo)
{
    const int t = blockIdx.x * 1024 + threadIdx.x;
    const float* Wo3 = Wo + (size_t)3 * E_ * E_;
    if (t < E_ * NCLS) {
        const int i = t / NCLS, c = t % NCLS;
        float s = 0.f;
        for (int k = 0; k < E_; ++k)
            s += Wo3[(size_t)i * E_ + k] * fc_w[k * NCLS + c];
        g_fcw[t] = s;
    }
    if (t < NCLS) {
        const float* bo3 = bo + (size_t)3 * E_;
        float s = fc_b[t];
        for (int k = 0; k < E_; ++k)
            s += bo3[k] * fc_w[k * NCLS + t];
        g_fcb[t] = s;
    }
}

__global__ __launch_bounds__(256, 2)
void gemm_qkv_g(const float* __restrict__ A,
                const float* __restrict__ Wq_, const float* __restrict__ Wk_,
                const float* __restrict__ Wv_,
                const float* __restrict__ bq_, const float* __restrict__ bk_,
                const float* __restrict__ bv_, int K)
{
    if (blockIdx.z == 0)
        gemm_body(A, Wq_, bq_, g_qh, g_ql, 0.125f, B_ * S_, K, E_);
    else if (blockIdx.z == 1)
        gemm_body(A, Wk_, bk_, g_k, nullptr, 1.f, B_ * S_, K, E_);
    else
        gemm_body(A, Wv_, bv_, g_v, nullptr, 1.f, B_ * S_, K, E_);
}

// ======================================================================
// Sparse attention (R11 + 2-MMA PV): 512 threads = 16 warps.
//  phase1: S = Q K^T, exact split-tf32 (3 MMA) — top-k stays exact
//  phase2: exact top-k (early-exit) + softmax
//  phase3: O = P V with P single-tf32, V split (2 MMA) — saves 1/3 MMAs
// ======================================================================
#define SP   1028
#define QP   68
#define KPR  68
#define VPR  72

#define ST_F (32 * SP)
#define QS_F (32 * QP)
#define KV_F (256 * VPR)
#define ATTN_SMEM ((ST_F + 2 * QS_F + KV_F) * 4)   // 222720 bytes

__global__ __launch_bounds__(512, 1)
void attn_kernel()
{
    extern __shared__ float sm[];
    float* St  = sm;
    float* Qsh = sm + ST_F;
    float* Qsl = Qsh + QS_F;
    float* KV  = Qsl + QS_F;

    const int t    = threadIdx.x;
    const int w    = t >> 5;
    const int lane = t & 31;
    const int grp  = lane >> 2;
    const int tg   = lane & 3;

    const int gid = blockIdx.x;
    const int qt  = gid & 31;
    const int hh  = (gid >> 5) & 7;
    const int b   = gid >> 8;

    const size_t qoff = ((size_t)(b * S_ + qt * QT)) * E_ + hh * D_;
    const size_t koff = ((size_t)b * S_) * E_ + hh * D_;

    const float* Qh = g_qh + qoff;
    const float* Ql = g_ql + qoff;
    const float* Kg = g_k + koff;
    const float* Vg = g_v + koff;
    float*       Og = g_o + qoff;

    {
        const int qi = t >> 4;
        const int d0 = (t & 15) * 4;
        float4 h4 = *(const float4*)(Qh + (size_t)qi * E_ + d0);
        float4 l4 = *(const float4*)(Ql + (size_t)qi * E_ + d0);
        *(float4*)&Qsh[qi * QP + d0] = h4;
        *(float4*)&Qsl[qi * QP + d0] = l4;
    }

    {
        float* Ksm = KV;
        for (int kc = 0; kc < S_; kc += 256) {
#pragma unroll
            for (int i = 0; i < 8; ++i) {
                int idx = t + i * 512;
                int row = idx >> 4;
                int c4  = (idx & 15) * 4;
                *(float4*)&Ksm[row * KPR + c4] =
                    *(const float4*)(Kg + (size_t)(kc + row) * E_ + c4);
            }
            __syncthreads();

            float acc[2][2][4];
#pragma unroll
            for (int mt = 0; mt < 2; ++mt)
#pragma unroll
                for (int nt = 0; nt < 2; ++nt)
#pragma unroll
                    for (int c = 0; c < 4; ++c) acc[mt][nt][c] = 0.f;

#pragma unroll
            for (int ks = 0; ks < 8; ++ks) {
                const int ka = ks * 8 + tg;
                unsigned ah[2][4], al[2][4];
#pragma unroll
                for (int mt = 0; mt < 2; ++mt) {
                    const int r = mt * 16 + grp;
                    ah[mt][0] = fu(Qsh[r * QP + ka]);
                    ah[mt][1] = fu(Qsh[(r + 8) * QP + ka]);
                    ah[mt][2] = fu(Qsh[r * QP + ka + 4]);
                    ah[mt][3] = fu(Qsh[(r + 8) * QP + ka + 4]);
                    al[mt][0] = fu(Qsl[r * QP + ka]);
                    al[mt][1] = fu(Qsl[(r + 8) * QP + ka]);
                    al[mt][2] = fu(Qsl[r * QP + ka + 4]);
                    al[mt][3] = fu(Qsl[(r + 8) * QP + ka + 4]);
                }
                unsigned bh[2][2], bl[2][2];
#pragma unroll
                for (int nt = 0; nt < 2; ++nt) {
                    const int key = w * 16 + nt * 8 + grp;
                    float y0 = Ksm[key * KPR + ka];
                    float y1 = Ksm[key * KPR + ka + 4];
                    float h0, l0, h1, l1;
                    split2(y0, h0, l0); split2(y1, h1, l1);
                    bh[nt][0] = fu(h0); bh[nt][1] = fu(h1);
                    bl[nt][0] = fu(l0); bl[nt][1] = fu(l1);
                }
#pragma unroll
                for (int mt = 0; mt < 2; ++mt)
#pragma unroll
                    for (int nt = 0; nt < 2; ++nt) {
                        mma_tf32(acc[mt][nt], ah[mt][0], ah[mt][1], ah[mt][2], ah[mt][3],
                                 bh[nt][0], bh[nt][1]);
                        mma_tf32(acc[mt][nt], ah[mt][0], ah[mt][1], ah[mt][2], ah[mt][3],
                                 bl[nt][0], bl[nt][1]);
                        mma_tf32(acc[mt][nt], al[mt][0], al[mt][1], al[mt][2], al[mt][3],
                                 bh[nt][0], bh[nt][1]);
                    }
            }
            const int keyb = kc + w * 16;
#pragma unroll
            for (int mt = 0; mt < 2; ++mt)
#pragma unroll
                for (int nt = 0; nt < 2; ++nt) {
                    const int q = mt * 16 + grp;
                    const int k = keyb + nt * 8 + 2 * tg;
                    *(float2*)&St[(size_t)q * SP + k] =
                        make_float2(acc[mt][nt][0], acc[mt][nt][1]);
                    *(float2*)&St[(size_t)(q + 8) * SP + k] =
                        make_float2(acc[mt][nt][2], acc[mt][nt][3]);
                }
            __syncthreads();
        }
    }

#pragma unroll
    for (int qq = 0; qq < 2; ++qq) {
        const int qi = w * 2 + qq;
        float* row = St + (size_t)qi * SP;

        unsigned u[32];
        unsigned umax = 0u, umin = 0xFFFFFFFFu;
#pragma unroll
        for (int i = 0; i < 32; ++i) {
            u[i] = fmap(row[lane + 32 * i]);
            umax = max(umax, u[i]);
            umin = min(umin, u[i]);
        }
        umax = __reduce_max_sync(0xFFFFFFFFu, umax);
        umin = __reduce_min_sync(0xFFFFFFFFu, umin);

        unsigned lo = umin, hi = umax, thr;
        for (;;) {
            if (lo >= hi) { thr = lo; break; }
            unsigned mid = lo + ((hi - lo + 1) >> 1);
            unsigned c = 0;
#pragma unroll
            for (int i = 0; i < 32; ++i) c += (u[i] >= mid);
            c = __reduce_add_sync(0xFFFFFFFFu, c);
            if (c == KTOP) { thr = mid; break; }
            if (c > KTOP) lo = mid; else hi = mid - 1;
        }
        const float mf = unfmap(umax);

        float sum = 0.f;
#pragma unroll
        for (int i = 0; i < 32; ++i) {
            float ev = 0.f;
            if (u[i] >= thr) ev = __expf(unfmap(u[i]) - mf);
            u[i] = __float_as_uint(ev);
            sum += ev;
        }
#pragma unroll
        for (int off = 16; off > 0; off >>= 1)
            sum += __shfl_xor_sync(0xFFFFFFFFu, sum, off);
        const float inv = 1.f / sum;

#pragma unroll
        for (int i = 0; i < 32; ++i)
            row[lane + 32 * i] = __uint_as_float(u[i]) * inv;
    }
    __syncthreads();

    // ---- phase 3: O = P V ; P single-tf32, V split -> 2 MMAs/frag ----
    {
        float* Vsm = KV;
        const int kg = w >> 2;
        const int wn = w & 3;

        float acc[2][2][4];
#pragma unroll
        for (int mt = 0; mt < 2; ++mt)
#pragma unroll
            for (int nt = 0; nt < 2; ++nt)
#pragma unroll
                for (int c = 0; c < 4; ++c) acc[mt][nt][c] = 0.f;

        for (int kc = 0; kc < S_; kc += 256) {
#pragma unroll
            for (int i = 0; i < 8; ++i) {
                int idx = t + i * 512;
                int row = idx >> 4;
                int c4  = (idx & 15) * 4;
                *(float4*)&Vsm[row * VPR + c4] =
                    *(const float4*)(Vg + (size_t)(kc + row) * E_ + c4);
            }
            __syncthreads();

#pragma unroll
            for (int ks = 0; ks < 8; ++ks) {
                const int kl = kg * 64 + ks * 8;
                const int k0 = kc + kl;

                unsigned bh[2][2], bl[2][2];
#pragma unroll
                for (int nt = 0; nt < 2; ++nt) {
                    const int col = wn * 16 + nt * 8 + grp;
                    float y0 = Vsm[(kl + tg) * VPR + col];
                    float y1 = Vsm[(kl + tg + 4) * VPR + col];
                    float h0, l0, h1, l1;
                    split2(y0, h0, l0); split2(y1, h1, l1);
                    bh[nt][0] = fu(h0); bh[nt][1] = fu(h1);
                    bl[nt][0] = fu(l0); bl[nt][1] = fu(l1);
                }
#pragma unroll
                for (int mt = 0; mt < 2; ++mt) {
                    // P: single tf32 (error ~2^-13 * P — dominated by output budget)
                    unsigned ah0 = fu(tf32f(St[(mt * 16 + grp) * SP + k0 + tg]));
                    unsigned ah1 = fu(tf32f(St[(mt * 16 + grp + 8) * SP + k0 + tg]));
                    unsigned ah2 = fu(tf32f(St[(mt * 16 + grp) * SP + k0 + tg + 4]));
                    unsigned ah3 = fu(tf32f(St[(mt * 16 + grp + 8) * SP + k0 + tg + 4]));
#pragma unroll
                    for (int nt = 0; nt < 2; ++nt) {
                        mma_tf32(acc[mt][nt], ah0, ah1, ah2, ah3, bh[nt][0], bh[nt][1]);
                        mma_tf32(acc[mt][nt], ah0, ah1, ah2, ah3, bl[nt][0], bl[nt][1]);
                    }
                }
            }
            __syncthreads();
        }

        float* red = KV;
#pragma unroll
        for (int mt = 0; mt < 2; ++mt)
#pragma unroll
            for (int nt = 0; nt < 2; ++nt) {
                const int q = mt * 16 + grp;
                const int d = wn * 16 + nt * 8 + 2 * tg;
                *(float2*)&red[kg * 2176 + q * 68 + d] =
                    make_float2(acc[mt][nt][0], acc[mt][nt][1]);
                *(float2*)&red[kg * 2176 + (q + 8) * 68 + d] =
                    make_float2(acc[mt][nt][2], acc[mt][nt][3]);
            }
        __syncthreads();

#pragma unroll
        for (int kk = 0; kk < 4; ++kk) {
            int m  = t + kk * 512;
            int qi = m >> 6, dd = m & 63;
            float s = red[0 * 2176 + qi * 68 + dd] + red[1 * 2176 + qi * 68 + dd]
                    + red[2 * 2176 + qi * 68 + dd] + red[3 * 2176 + qi * 68 + dd];
            Og[(size_t)qi * E_ + dd] = s;
        }
    }
}

// ======================================================================
// mean pool + final FC
// ======================================================================
__global__ void meanpool_k(const float* __restrict__ h, float* __restrict__ pool)
{
    __shared__ float red[512];
    const int b = blockIdx.y;
    const int e = blockIdx.x * 128 + (threadIdx.x & 127);
    const int slice = threadIdx.x >> 7;
    const float* base = h + (size_t)b * S_ * E_ + e;
    float s = 0.f;
#pragma unroll 8
    for (int i = 0; i < 256; ++i)
        s += base[(size_t)(slice * 256 + i) * E_];
    red[threadIdx.x] = s;
    __syncthreads();
    if (slice == 0) {
        float tot = red[threadIdx.x] + red[threadIdx.x + 128] +
                    red[threadIdx.x + 256] + red[threadIdx.x + 384];
        pool[b * E_ + e] = tot * (1.f / (float)S_);
    }
}

__global__ void fc_k(const float* __restrict__ pool, const float* __restrict__ w,
                     const float* __restrict__ bias, float* __restrict__ out)
{
    int t = threadIdx.x;
    if (t >= B_ * NCLS) return;
    int b = t / NCLS, c = t % NCLS;
    float s = bias[c];
    const float* p = pool + b * E_;
#pragma unroll 8
    for (int k = 0; k < E_; ++k)
        s += p[k] * w[k * NCLS + c];
    out[t] = s;
}

// ======================================================================
// launch
// ======================================================================
extern "C" void kernel_launch(void* const* d_in, const int* in_sizes, int n_in,
                              void* d_out, int out_size)
{
    (void)in_sizes; (void)n_in; (void)out_size;

    const float* x     = (const float*)d_in[0];
    const float* emb_w = (const float*)d_in[1];
    const float* emb_b = (const float*)d_in[2];
    const float* Wq    = (const float*)d_in[3];
    const float* Wk    = (const float*)d_in[4];
    const float* Wv    = (const float*)d_in[5];
    const float* Wo    = (const float*)d_in[6];
    const float* bq    = (const float*)d_in[7];
    const float* bk    = (const float*)d_in[8];
    const float* bv    = (const float*)d_in[9];
    const float* bo    = (const float*)d_in[10];
    const float* fc_w  = (const float*)d_in[11];
    const float* fc_b  = (const float*)d_in[12];
    float* out = (float*)d_out;

    float *o, *pool, *cw0, *cw, *cb, *fcw, *fcb;
    cudaGetSymbolAddress((void**)&o,    g_o);
    cudaGetSymbolAddress((void**)&pool, g_pool);
    cudaGetSymbolAddress((void**)&cw0,  g_cw0);
    cudaGetSymbolAddress((void**)&cw,   g_cw);
    cudaGetSymbolAddress((void**)&cb,   g_cb);
    cudaGetSymbolAddress((void**)&fcw,  g_fcw);
    cudaGetSymbolAddress((void**)&fcb,  g_fcb);

    cudaFuncSetAttribute(attn_kernel, cudaFuncAttributeMaxDynamicSharedMemorySize, ATTN_SMEM);
    cudaFuncSetAttribute(gemm_qkv_g,  cudaFuncAttributeMaxDynamicSharedMemorySize, GEMM_SMEM);
    cudaFuncSetAttribute(combine_w,   cudaFuncAttributeMaxDynamicSharedMemorySize, GEMM_SMEM);

    const int M = B_ * S_;                          // 8192
    dim3 qkvgrid(E_ / 128, M / 128, 3);             // (4, 64, 3)
    const int attn_grid = B_ * H_ * (S_ / QT);      // 2048

    // ---- weight/bias folding ----
    combine_w<<<dim3(4, 4, 12), 256, GEMM_SMEM>>>(emb_w, Wq, Wk, Wv, Wo);
    combine_b<<<12, E_>>>(emb_b, Wq, Wk, Wv, bq, bk, bv, bo);
    fc_fold<<<5, 1024>>>(Wo, fc_w, fc_b, bo);

    // ---- layer 0: QKV directly from x (K = FIN = 128) ----
    gemm_qkv_g<<<qkvgrid, 256, GEMM_SMEM>>>(
        x, cw0, cw0 + FIN * E_, cw0 + 2 * FIN * E_,
        cb, cb + E_, cb + 2 * E_, FIN);
    attn_kernel<<<attn_grid, 512, ATTN_SMEM>>>();

    // ---- layers 1..3: QKV from o with folded Wo (K = 512) ----
    for (int l = 1; l < L_; ++l) {
        const size_t wb = (size_t)(l - 1) * 3 * E_ * E_;
        const size_t bb = (size_t)l * 3 * E_;
        gemm_qkv_g<<<qkvgrid, 256, GEMM_SMEM>>>(
            o, cw + wb, cw + wb + (size_t)E_ * E_, cw + wb + (size_t)2 * E_ * E_,
            cb + bb, cb + bb + E_, cb + bb + 2 * E_, E_);
        attn_kernel<<<attn_grid, 512, ATTN_SMEM>>>();
    }

    // ---- pool over o3, FC with folded weights ----
    meanpool_k<<<dim3(E_ / 128, B_), 512>>>(o, pool);
    fc_k<<<1, 128>>>(pool, fcw, fcb, out);
}

// round 15
// speedup vs baseline: 1.1463x; 1.0536x over previous
#include <cuda_runtime.h>
#include <math.h>

// ---------------- problem constants ----------------
#define B_   8
#define S_   1024
#define E_   512
#define H_   8
#define D_   64
#define L_   4
#define KTOP 256
#define FIN  128
#define NCLS 10
#define QT   32

// ---------------- device scratch ----------------
__device__ float g_o [(size_t)B_ * S_ * E_];
__device__ float g_qh[(size_t)B_ * S_ * E_];
__device__ float g_ql[(size_t)B_ * S_ * E_];
__device__ float g_k [(size_t)B_ * S_ * E_];
__device__ float g_v [(size_t)B_ * S_ * E_];
__device__ float g_pool[B_ * E_];
__device__ float g_zero[E_];                       // zero-initialized
// combined weights/biases
__device__ float g_cw0[3 * FIN * E_];              // layer0: emb_w @ W{q,k,v}0
__device__ float g_cw [9 * E_ * E_];               // layers1-3: Wo_{l-1} @ W{q,k,v}_l
__device__ float g_cb [12 * E_];                   // combined biases [l*3+j]
__device__ float g_fcw[E_ * NCLS];                 // Wo3 @ fc_w
__device__ float g_fcb[NCLS];                      // bo3 @ fc_w + fc_b

// ---------------- helpers ----------------
__device__ __forceinline__ float tf32f(float x) {
    unsigned u;
    asm("cvt.rna.tf32.f32 %0, %1;" : "=r"(u) : "f"(x));
    return __uint_as_float(u);
}
__device__ __forceinline__ void mma_tf32(float c[4],
    unsigned a0, unsigned a1, unsigned a2, unsigned a3,
    unsigned b0, unsigned b1)
{
    asm volatile(
        "mma.sync.aligned.m16n8k8.row.col.f32.tf32.tf32.f32 "
        "{%0,%1,%2,%3},{%4,%5,%6,%7},{%8,%9},{%0,%1,%2,%3};"
        : "+f"(c[0]), "+f"(c[1]), "+f"(c[2]), "+f"(c[3])
        : "r"(a0), "r"(a1), "r"(a2), "r"(a3), "r"(b0), "r"(b1));
}
__device__ __forceinline__ unsigned fu(float x) { return __float_as_uint(x); }

__device__ __forceinline__ unsigned fmap(float x) {
    unsigned u = __float_as_uint(x);
    return (u & 0x80000000u) ? ~u : (u | 0x80000000u);
}
__device__ __forceinline__ float unfmap(unsigned u) {
    return (u & 0x80000000u) ? __uint_as_float(u & 0x7FFFFFFFu)
                             : __uint_as_float(~u);
}
__device__ __forceinline__ void split2(float x, float& h, float& l) {
    h = tf32f(x);
    l = tf32f(x - h);
}

// ======================================================================
// split-tf32 GEMM (R4/R9 form: split at smem-store, synchronous loop).
// C = A[M,K] @ W[K,N] + bias. 128x128 tile, BK=32, 256 thr = 8 warps.
// Optional split-output epilogue: (acc+bias)*scale -> hi/lo planes.
// ======================================================================
#define GA 36
#define GB 136
#define GEMM_SMEM ((128*GA*2 + 32*GB*2) * 4)   // 71680 bytes

__device__ __forceinline__
void gemm_body(const float* __restrict__ A, const float* __restrict__ W,
               const float* __restrict__ bias,
               float* __restrict__ Ch, float* __restrict__ Cl, float scale,
               int M, int K, int N)
{
    extern __shared__ float gsm[];
    float* Ash = gsm;
    float* Asl = Ash + 128 * GA;
    float* Bsh = Asl + 128 * GA;
    float* Bsl = Bsh + 32 * GB;

    const int t    = threadIdx.x;
    const int m0   = blockIdx.y * 128;
    const int n0   = blockIdx.x * 128;
    const int w    = t >> 5;
    const int lane = t & 31;
    const int wm   = w >> 2;
    const int wn   = w & 3;
    const int grp  = lane >> 2;
    const int tg   = lane & 3;

    float acc[4][4][4];
#pragma unroll
    for (int i = 0; i < 4; ++i)
#pragma unroll
        for (int j = 0; j < 4; ++j)
#pragma unroll
            for (int c = 0; c < 4; ++c) acc[i][j][c] = 0.f;

    const float* Aptr = A + (size_t)m0 * K;
    const float* Wptr = W + n0;

    for (int k0 = 0; k0 < K; k0 += 32) {
#pragma unroll
        for (int i = 0; i < 4; ++i) {
            int idx = t + i * 256;
            int row = idx >> 3;
            int c4  = (idx & 7) * 4;
            float4 v = *(const float4*)(Aptr + (size_t)row * K + k0 + c4);
            float h0, l0, h1, l1, h2, l2, h3, l3;
            split2(v.x, h0, l0); split2(v.y, h1, l1);
            split2(v.z, h2, l2); split2(v.w, h3, l3);
            *(float4*)&Ash[row * GA + c4] = make_float4(h0, h1, h2, h3);
            *(float4*)&Asl[row * GA + c4] = make_float4(l0, l1, l2, l3);
        }
#pragma unroll
        for (int i = 0; i < 4; ++i) {
            int idx = t + i * 256;
            int row = idx >> 5;
            int c4  = (idx & 31) * 4;
            float4 v = *(const float4*)(Wptr + (size_t)(k0 + row) * N + c4);
            float h0, l0, h1, l1, h2, l2, h3, l3;
            split2(v.x, h0, l0); split2(v.y, h1, l1);
            split2(v.z, h2, l2); split2(v.w, h3, l3);
            *(float4*)&Bsh[row * GB + c4] = make_float4(h0, h1, h2, h3);
            *(float4*)&Bsl[row * GB + c4] = make_float4(l0, l1, l2, l3);
        }
        __syncthreads();

#pragma unroll
        for (int ks = 0; ks < 4; ++ks) {
            const int ka = ks * 8 + tg;
            unsigned bh[4][2], bl[4][2];
#pragma unroll
            for (int nt = 0; nt < 4; ++nt) {
                int c = wn * 32 + nt * 8 + grp;
                bh[nt][0] = fu(Bsh[ka * GB + c]);
                bh[nt][1] = fu(Bsh[(ka + 4) * GB + c]);
                bl[nt][0] = fu(Bsl[ka * GB + c]);
                bl[nt][1] = fu(Bsl[(ka + 4) * GB + c]);
            }
#pragma unroll
            for (int mt = 0; mt < 4; ++mt) {
                int r = wm * 64 + mt * 16 + grp;
                unsigned ah0 = fu(Ash[r * GA + ka]);
                unsigned ah1 = fu(Ash[(r + 8) * GA + ka]);
                unsigned ah2 = fu(Ash[r * GA + ka + 4]);
                unsigned ah3 = fu(Ash[(r + 8) * GA + ka + 4]);
                unsigned al0 = fu(Asl[r * GA + ka]);
                unsigned al1 = fu(Asl[(r + 8) * GA + ka]);
                unsigned al2 = fu(Asl[r * GA + ka + 4]);
                unsigned al3 = fu(Asl[(r + 8) * GA + ka + 4]);
#pragma unroll
                for (int nt = 0; nt < 4; ++nt) {
                    mma_tf32(acc[mt][nt], ah0, ah1, ah2, ah3, bh[nt][0], bh[nt][1]);
                    mma_tf32(acc[mt][nt], ah0, ah1, ah2, ah3, bl[nt][0], bl[nt][1]);
                    mma_tf32(acc[mt][nt], al0, al1, al2, al3, bh[nt][0], bh[nt][1]);
                }
            }
        }
        __syncthreads();
    }

    if (Cl == nullptr) {
#pragma unroll
        for (int nt = 0; nt < 4; ++nt) {
            const int c = n0 + wn * 32 + nt * 8 + 2 * tg;
            float2 bv = *(const float2*)&bias[c];
#pragma unroll
            for (int mt = 0; mt < 4; ++mt) {
                int r = m0 + wm * 64 + mt * 16 + grp;
                float2 r0 = make_float2(acc[mt][nt][0] + bv.x, acc[mt][nt][1] + bv.y);
                float2 r1 = make_float2(acc[mt][nt][2] + bv.x, acc[mt][nt][3] + bv.y);
                *(float2*)&Ch[(size_t)r * N + c]       = r0;
                *(float2*)&Ch[(size_t)(r + 8) * N + c] = r1;
            }
        }
    } else {
#pragma unroll
        for (int nt = 0; nt < 4; ++nt) {
            const int c = n0 + wn * 32 + nt * 8 + 2 * tg;
            float2 bv = *(const float2*)&bias[c];
#pragma unroll
            for (int mt = 0; mt < 4; ++mt) {
                int r = m0 + wm * 64 + mt * 16 + grp;
                float v00 = (acc[mt][nt][0] + bv.x) * scale;
                float v01 = (acc[mt][nt][1] + bv.y) * scale;
                float v10 = (acc[mt][nt][2] + bv.x) * scale;
                float v11 = (acc[mt][nt][3] + bv.y) * scale;
                float h00, l00, h01, l01, h10, l10, h11, l11;
                split2(v00, h00, l00); split2(v01, h01, l01);
                split2(v10, h10, l10); split2(v11, h11, l11);
                *(float2*)&Ch[(size_t)r * N + c]       = make_float2(h00, h01);
                *(float2*)&Ch[(size_t)(r + 8) * N + c] = make_float2(h10, h11);
                *(float2*)&Cl[(size_t)r * N + c]       = make_float2(l00, l01);
                *(float2*)&Cl[(size_t)(r + 8) * N + c] = make_float2(l10, l11);
            }
        }
    }
}

// ---- weight combination: grid (4, 4, 12) ----
__global__ __launch_bounds__(256, 2)
void combine_w(const float* __restrict__ emb_w,
               const float* __restrict__ Wq, const float* __restrict__ Wk,
               const float* __restrict__ Wv, const float* __restrict__ Wo)
{
    const int z = blockIdx.z;
    if (z < 9) {
        const int l = z / 3 + 1, j = z % 3;
        const float* Wsel = (j == 0 ? Wq : j == 1 ? Wk : Wv) + (size_t)l * E_ * E_;
        gemm_body(Wo + (size_t)(l - 1) * E_ * E_, Wsel, g_zero,
                  g_cw + (size_t)z * E_ * E_, nullptr, 1.f, E_, E_, E_);
    } else {
        if (blockIdx.y != 0) return;
        const int j = z - 9;
        const float* Wsel = (j == 0 ? Wq : j == 1 ? Wk : Wv);
        gemm_body(emb_w, Wsel, g_zero,
                  g_cw0 + (size_t)j * FIN * E_, nullptr, 1.f, FIN, E_, E_);
    }
}

__global__ void combine_b(const float* __restrict__ emb_b,
                          const float* __restrict__ Wq, const float* __restrict__ Wk,
                          const float* __restrict__ Wv,
                          const float* __restrict__ bq, const float* __restrict__ bk,
                          const float* __restrict__ bv, const float* __restrict__ bo)
{
    const int l = blockIdx.x / 3, j = blockIdx.x % 3;
    const int t = threadIdx.x;
    const float* W = (j == 0 ? Wq : j == 1 ? Wk : Wv) + (size_t)l * E_ * E_;
    const float* badd = (j == 0 ? bq : j == 1 ? bk : bv) + (size_t)l * E_;
    float s = 0.f;
    if (l == 0) {
        for (int k = 0; k < FIN; ++k) s += emb_b[k] * W[(size_t)k * E_ + t];
    } else {
        const float* bvp = bo + (size_t)(l - 1) * E_;
        for (int k = 0; k < E_; ++k) s += bvp[k] * W[(size_t)k * E_ + t];
    }
    g_cb[blockIdx.x * E_ + t] = s + badd[t];
}

__global__ void fc_fold(const float* __restrict__ Wo, const float* __restrict__ fc_w,
                        const float* __restrict__ fc_b, const float* __restrict__ bo)
{
    const int t = blockIdx.x * 1024 + threadIdx.x;
    const float* Wo3 = Wo + (size_t)3 * E_ * E_;
    if (t < E_ * NCLS) {
        const int i = t / NCLS, c = t % NCLS;
        float s = 0.f;
        for (int k = 0; k < E_; ++k)
            s += Wo3[(size_t)i * E_ + k] * fc_w[k * NCLS + c];
        g_fcw[t] = s;
    }
    if (t < NCLS) {
        const float* bo3 = bo + (size_t)3 * E_;
        float s = fc_b[t];
        for (int k = 0; k < E_; ++k)
            s += bo3[k] * fc_w[k * NCLS + t];
        g_fcb[t] = s;
    }
}

__global__ __launch_bounds__(256, 2)
void gemm_qkv_g(const float* __restrict__ A,
                const float* __restrict__ Wq_, const float* __restrict__ Wk_,
                const float* __restrict__ Wv_,
                const float* __restrict__ bq_, const float* __restrict__ bk_,
                const float* __restrict__ bv_, int K)
{
    if (blockIdx.z == 0)
        gemm_body(A, Wq_, bq_, g_qh, g_ql, 0.125f, B_ * S_, K, E_);
    else if (blockIdx.z == 1)
        gemm_body(A, Wk_, bk_, g_k, nullptr, 1.f, B_ * S_, K, E_);
    else
        gemm_body(A, Wv_, bv_, g_v, nullptr, 1.f, B_ * S_, K, E_);
}

// ======================================================================
// Sparse attention (R14 + 1-MMA PV): 512 threads = 16 warps.
//  phase1: S = Q K^T, exact split-tf32 (3 MMA) — top-k stays exact
//  phase2: exact top-k (early-exit) + softmax
//  phase3: O = P V with P AND V single-tf32 (1 MMA) — V path is
//          linear output noise only, never touches top-k selection
// ======================================================================
#define SP   1028
#define QP   68
#define KPR  68
#define VPR  72

#define ST_F (32 * SP)
#define QS_F (32 * QP)
#define KV_F (256 * VPR)
#define ATTN_SMEM ((ST_F + 2 * QS_F + KV_F) * 4)   // 222720 bytes

__global__ __launch_bounds__(512, 1)
void attn_kernel()
{
    extern __shared__ float sm[];
    float* St  = sm;
    float* Qsh = sm + ST_F;
    float* Qsl = Qsh + QS_F;
    float* KV  = Qsl + QS_F;

    const int t    = threadIdx.x;
    const int w    = t >> 5;
    const int lane = t & 31;
    const int grp  = lane >> 2;
    const int tg   = lane & 3;

    const int gid = blockIdx.x;
    const int qt  = gid & 31;
    const int hh  = (gid >> 5) & 7;
    const int b   = gid >> 8;

    const size_t qoff = ((size_t)(b * S_ + qt * QT)) * E_ + hh * D_;
    const size_t koff = ((size_t)b * S_) * E_ + hh * D_;

    const float* Qh = g_qh + qoff;
    const float* Ql = g_ql + qoff;
    const float* Kg = g_k + koff;
    const float* Vg = g_v + koff;
    float*       Og = g_o + qoff;

    {
        const int qi = t >> 4;
        const int d0 = (t & 15) * 4;
        float4 h4 = *(const float4*)(Qh + (size_t)qi * E_ + d0);
        float4 l4 = *(const float4*)(Ql + (size_t)qi * E_ + d0);
        *(float4*)&Qsh[qi * QP + d0] = h4;
        *(float4*)&Qsl[qi * QP + d0] = l4;
    }

    {
        float* Ksm = KV;
        for (int kc = 0; kc < S_; kc += 256) {
#pragma unroll
            for (int i = 0; i < 8; ++i) {
                int idx = t + i * 512;
                int row = idx >> 4;
                int c4  = (idx & 15) * 4;
                *(float4*)&Ksm[row * KPR + c4] =
                    *(const float4*)(Kg + (size_t)(kc + row) * E_ + c4);
            }
            __syncthreads();

            float acc[2][2][4];
#pragma unroll
            for (int mt = 0; mt < 2; ++mt)
#pragma unroll
                for (int nt = 0; nt < 2; ++nt)
#pragma unroll
                    for (int c = 0; c < 4; ++c) acc[mt][nt][c] = 0.f;

#pragma unroll
            for (int ks = 0; ks < 8; ++ks) {
                const int ka = ks * 8 + tg;
                unsigned ah[2][4], al[2][4];
#pragma unroll
                for (int mt = 0; mt < 2; ++mt) {
                    const int r = mt * 16 + grp;
                    ah[mt][0] = fu(Qsh[r * QP + ka]);
                    ah[mt][1] = fu(Qsh[(r + 8) * QP + ka]);
                    ah[mt][2] = fu(Qsh[r * QP + ka + 4]);
                    ah[mt][3] = fu(Qsh[(r + 8) * QP + ka + 4]);
                    al[mt][0] = fu(Qsl[r * QP + ka]);
                    al[mt][1] = fu(Qsl[(r + 8) * QP + ka]);
                    al[mt][2] = fu(Qsl[r * QP + ka + 4]);
                    al[mt][3] = fu(Qsl[(r + 8) * QP + ka + 4]);
                }
                unsigned bh[2][2], bl[2][2];
#pragma unroll
                for (int nt = 0; nt < 2; ++nt) {
                    const int key = w * 16 + nt * 8 + grp;
                    float y0 = Ksm[key * KPR + ka];
                    float y1 = Ksm[key * KPR + ka + 4];
                    float h0, l0, h1, l1;
                    split2(y0, h0, l0); split2(y1, h1, l1);
                    bh[nt][0] = fu(h0); bh[nt][1] = fu(h1);
                    bl[nt][0] = fu(l0); bl[nt][1] = fu(l1);
                }
#pragma unroll
                for (int mt = 0; mt < 2; ++mt)
#pragma unroll
                    for (int nt = 0; nt < 2; ++nt) {
                        mma_tf32(acc[mt][nt], ah[mt][0], ah[mt][1], ah[mt][2], ah[mt][3],
                                 bh[nt][0], bh[nt][1]);
                        mma_tf32(acc[mt][nt], ah[mt][0], ah[mt][1], ah[mt][2], ah[mt][3],
                                 bl[nt][0], bl[nt][1]);
                        mma_tf32(acc[mt][nt], al[mt][0], al[mt][1], al[mt][2], al[mt][3],
                                 bh[nt][0], bh[nt][1]);
                    }
            }
            const int keyb = kc + w * 16;
#pragma unroll
            for (int mt = 0; mt < 2; ++mt)
#pragma unroll
                for (int nt = 0; nt < 2; ++nt) {
                    const int q = mt * 16 + grp;
                    const int k = keyb + nt * 8 + 2 * tg;
                    *(float2*)&St[(size_t)q * SP + k] =
                        make_float2(acc[mt][nt][0], acc[mt][nt][1]);
                    *(float2*)&St[(size_t)(q + 8) * SP + k] =
                        make_float2(acc[mt][nt][2], acc[mt][nt][3]);
                }
            __syncthreads();
        }
    }

#pragma unroll
    for (int qq = 0; qq < 2; ++qq) {
        const int qi = w * 2 + qq;
        float* row = St + (size_t)qi * SP;

        unsigned u[32];
        unsigned umax = 0u, umin = 0xFFFFFFFFu;
#pragma unroll
        for (int i = 0; i < 32; ++i) {
            u[i] = fmap(row[lane + 32 * i]);
            umax = max(umax, u[i]);
            umin = min(umin, u[i]);
        }
        umax = __reduce_max_sync(0xFFFFFFFFu, umax);
        umin = __reduce_min_sync(0xFFFFFFFFu, umin);

        unsigned lo = umin, hi = umax, thr;
        for (;;) {
            if (lo >= hi) { thr = lo; break; }
            unsigned mid = lo + ((hi - lo + 1) >> 1);
            unsigned c = 0;
#pragma unroll
            for (int i = 0; i < 32; ++i) c += (u[i] >= mid);
            c = __reduce_add_sync(0xFFFFFFFFu, c);
            if (c == KTOP) { thr = mid; break; }
            if (c > KTOP) lo = mid; else hi = mid - 1;
        }
        const float mf = unfmap(umax);

        float sum = 0.f;
#pragma unroll
        for (int i = 0; i < 32; ++i) {
            float ev = 0.f;
            if (u[i] >= thr) ev = __expf(unfmap(u[i]) - mf);
            u[i] = __float_as_uint(ev);
            sum += ev;
        }
#pragma unroll
        for (int off = 16; off > 0; off >>= 1)
            sum += __shfl_xor_sync(0xFFFFFFFFu, sum, off);
        const float inv = 1.f / sum;

#pragma unroll
        for (int i = 0; i < 32; ++i)
            row[lane + 32 * i] = __uint_as_float(u[i]) * inv;
    }
    __syncthreads();

    // ---- phase 3: O = P V ; P and V single-tf32 -> 1 MMA/frag ----
    {
        float* Vsm = KV;
        const int kg = w >> 2;
        const int wn = w & 3;

        float acc[2][2][4];
#pragma unroll
        for (int mt = 0; mt < 2; ++mt)
#pragma unroll
            for (int nt = 0; nt < 2; ++nt)
#pragma unroll
                for (int c = 0; c < 4; ++c) acc[mt][nt][c] = 0.f;

        for (int kc = 0; kc < S_; kc += 256) {
#pragma unroll
            for (int i = 0; i < 8; ++i) {
                int idx = t + i * 512;
                int row = idx >> 4;
                int c4  = (idx & 15) * 4;
                *(float4*)&Vsm[row * VPR + c4] =
                    *(const float4*)(Vg + (size_t)(kc + row) * E_ + c4);
            }
            __syncthreads();

#pragma unroll
            for (int ks = 0; ks < 8; ++ks) {
                const int kl = kg * 64 + ks * 8;
                const int k0 = kc + kl;

                unsigned bh[2][2];
#pragma unroll
                for (int nt = 0; nt < 2; ++nt) {
                    const int col = wn * 16 + nt * 8 + grp;
                    bh[nt][0] = fu(tf32f(Vsm[(kl + tg) * VPR + col]));
                    bh[nt][1] = fu(tf32f(Vsm[(kl + tg + 4) * VPR + col]));
                }
#pragma unroll
                for (int mt = 0; mt < 2; ++mt) {
                    unsigned ah0 = fu(tf32f(St[(mt * 16 + grp) * SP + k0 + tg]));
                    unsigned ah1 = fu(tf32f(St[(mt * 16 + grp + 8) * SP + k0 + tg]));
                    unsigned ah2 = fu(tf32f(St[(mt * 16 + grp) * SP + k0 + tg + 4]));
                    unsigned ah3 = fu(tf32f(St[(mt * 16 + grp + 8) * SP + k0 + tg + 4]));
#pragma unroll
                    for (int nt = 0; nt < 2; ++nt)
                        mma_tf32(acc[mt][nt], ah0, ah1, ah2, ah3, bh[nt][0], bh[nt][1]);
                }
            }
            __syncthreads();
        }

        float* red = KV;
#pragma unroll
        for (int mt = 0; mt < 2; ++mt)
#pragma unroll
            for (int nt = 0; nt < 2; ++nt) {
                const int q = mt * 16 + grp;
                const int d = wn * 16 + nt * 8 + 2 * tg;
                *(float2*)&red[kg * 2176 + q * 68 + d] =
                    make_float2(acc[mt][nt][0], acc[mt][nt][1]);
                *(float2*)&red[kg * 2176 + (q + 8) * 68 + d] =
                    make_float2(acc[mt][nt][2], acc[mt][nt][3]);
            }
        __syncthreads();

#pragma unroll
        for (int kk = 0; kk < 4; ++kk) {
            int m  = t + kk * 512;
            int qi = m >> 6, dd = m & 63;
            float s = red[0 * 2176 + qi * 68 + dd] + red[1 * 2176 + qi * 68 + dd]
                    + red[2 * 2176 + qi * 68 + dd] + red[3 * 2176 + qi * 68 + dd];
            Og[(size_t)qi * E_ + dd] = s;
        }
    }
}

// ======================================================================
// mean pool + final FC
// ======================================================================
__global__ void meanpool_k(const float* __restrict__ h, float* __restrict__ pool)
{
    __shared__ float red[512];
    const int b = blockIdx.y;
    const int e = blockIdx.x * 128 + (threadIdx.x & 127);
    const int slice = threadIdx.x >> 7;
    const float* base = h + (size_t)b * S_ * E_ + e;
    float s = 0.f;
#pragma unroll 8
    for (int i = 0; i < 256; ++i)
        s += base[(size_t)(slice * 256 + i) * E_];
    red[threadIdx.x] = s;
    __syncthreads();
    if (slice == 0) {
        float tot = red[threadIdx.x] + red[threadIdx.x + 128] +
                    red[threadIdx.x + 256] + red[threadIdx.x + 384];
        pool[b * E_ + e] = tot * (1.f / (float)S_);
    }
}

__global__ void fc_k(const float* __restrict__ pool, const float* __restrict__ w,
                     const float* __restrict__ bias, float* __restrict__ out)
{
    int t = threadIdx.x;
    if (t >= B_ * NCLS) return;
    int b = t / NCLS, c = t % NCLS;
    float s = bias[c];
    const float* p = pool + b * E_;
#pragma unroll 8
    for (int k = 0; k < E_; ++k)
        s += p[k] * w[k * NCLS + c];
    out[t] = s;
}

// ======================================================================
// launch
// ======================================================================
extern "C" void kernel_launch(void* const* d_in, const int* in_sizes, int n_in,
                              void* d_out, int out_size)
{
    (void)in_sizes; (void)n_in; (void)out_size;

    const float* x     = (const float*)d_in[0];
    const float* emb_w = (const float*)d_in[1];
    const float* emb_b = (const float*)d_in[2];
    const float* Wq    = (const float*)d_in[3];
    const float* Wk    = (const float*)d_in[4];
    const float* Wv    = (const float*)d_in[5];
    const float* Wo    = (const float*)d_in[6];
    const float* bq    = (const float*)d_in[7];
    const float* bk    = (const float*)d_in[8];
    const float* bv    = (const float*)d_in[9];
    const float* bo    = (const float*)d_in[10];
    const float* fc_w  = (const float*)d_in[11];
    const float* fc_b  = (const float*)d_in[12];
    float* out = (float*)d_out;

    float *o, *pool, *cw0, *cw, *cb, *fcw, *fcb;
    cudaGetSymbolAddress((void**)&o,    g_o);
    cudaGetSymbolAddress((void**)&pool, g_pool);
    cudaGetSymbolAddress((void**)&cw0,  g_cw0);
    cudaGetSymbolAddress((void**)&cw,   g_cw);
    cudaGetSymbolAddress((void**)&cb,   g_cb);
    cudaGetSymbolAddress((void**)&fcw,  g_fcw);
    cudaGetSymbolAddress((void**)&fcb,  g_fcb);

    cudaFuncSetAttribute(attn_kernel, cudaFuncAttributeMaxDynamicSharedMemorySize, ATTN_SMEM);
    cudaFuncSetAttribute(gemm_qkv_g,  cudaFuncAttributeMaxDynamicSharedMemorySize, GEMM_SMEM);
    cudaFuncSetAttribute(combine_w,   cudaFuncAttributeMaxDynamicSharedMemorySize, GEMM_SMEM);

    const int M = B_ * S_;                          // 8192
    dim3 qkvgrid(E_ / 128, M / 128, 3);             // (4, 64, 3)
    const int attn_grid = B_ * H_ * (S_ / QT);      // 2048

    // ---- weight/bias folding ----
    combine_w<<<dim3(4, 4, 12), 256, GEMM_SMEM>>>(emb_w, Wq, Wk, Wv, Wo);
    combine_b<<<12, E_>>>(emb_b, Wq, Wk, Wv, bq, bk, bv, bo);
    fc_fold<<<5, 1024>>>(Wo, fc_w, fc_b, bo);

    // ---- layer 0: QKV directly from x (K = FIN = 128) ----
    gemm_qkv_g<<<qkvgrid, 256, GEMM_SMEM>>>(
        x, cw0, cw0 + FIN * E_, cw0 + 2 * FIN * E_,
        cb, cb + E_, cb + 2 * E_, FIN);
    attn_kernel<<<attn_grid, 512, ATTN_SMEM>>>();

    // ---- layers 1..3: QKV from o with folded Wo (K = 512) ----
    for (int l = 1; l < L_; ++l) {
        const size_t wb = (size_t)(l - 1) * 3 * E_ * E_;
        const size_t bb = (size_t)l * 3 * E_;
        gemm_qkv_g<<<qkvgrid, 256, GEMM_SMEM>>>(
            o, cw + wb, cw + wb + (size_t)E_ * E_, cw + wb + (size_t)2 * E_ * E_,
            cb + bb, cb + bb + E_, cb + bb + 2 * E_, E_);
        attn_kernel<<<attn_grid, 512, ATTN_SMEM>>>();
    }

    // ---- pool over o3, FC with folded weights ----
    meanpool_k<<<dim3(E_ / 128, B_), 512>>>(o, pool);
    fc_k<<<1, 128>>>(pool, fcw, fcb, out);
}

// round 16
// speedup vs baseline: 1.2250x; 1.0687x over previous
#include <cuda_runtime.h>
#include <math.h>

// ---------------- problem constants ----------------
#define B_   8
#define S_   1024
#define E_   512
#define H_   8
#define D_   64
#define L_   4
#define KTOP 256
#define FIN  128
#define NCLS 10
#define QT   32

// ---------------- device scratch ----------------
__device__ float g_o [(size_t)B_ * S_ * E_];
__device__ float g_qh[(size_t)B_ * S_ * E_];
__device__ float g_ql[(size_t)B_ * S_ * E_];
__device__ float g_k [(size_t)B_ * S_ * E_];
__device__ float g_v [(size_t)B_ * S_ * E_];
__device__ float g_pool[B_ * E_];
__device__ float g_zero[E_];                       // zero-initialized
// combined weights/biases
__device__ float g_cw0[3 * FIN * E_];              // layer0: emb_w @ W{q,k,v}0
__device__ float g_cw [9 * E_ * E_];               // layers1-3: Wo_{l-1} @ W{q,k,v}_l
__device__ float g_cb [12 * E_];                   // combined biases [l*3+j]
__device__ float g_fcw[E_ * NCLS];                 // Wo3 @ fc_w
__device__ float g_fcb[NCLS];                      // bo3 @ fc_w + fc_b

// ---------------- helpers ----------------
__device__ __forceinline__ float tf32f(float x) {
    unsigned u;
    asm("cvt.rna.tf32.f32 %0, %1;" : "=r"(u) : "f"(x));
    return __uint_as_float(u);
}
__device__ __forceinline__ void mma_tf32(float c[4],
    unsigned a0, unsigned a1, unsigned a2, unsigned a3,
    unsigned b0, unsigned b1)
{
    asm volatile(
        "mma.sync.aligned.m16n8k8.row.col.f32.tf32.tf32.f32 "
        "{%0,%1,%2,%3},{%4,%5,%6,%7},{%8,%9},{%0,%1,%2,%3};"
        : "+f"(c[0]), "+f"(c[1]), "+f"(c[2]), "+f"(c[3])
        : "r"(a0), "r"(a1), "r"(a2), "r"(a3), "r"(b0), "r"(b1));
}
__device__ __forceinline__ unsigned fu(float x) { return __float_as_uint(x); }

__device__ __forceinline__ unsigned fmap(float x) {
    unsigned u = __float_as_uint(x);
    return (u & 0x80000000u) ? ~u : (u | 0x80000000u);
}
__device__ __forceinline__ float unfmap(unsigned u) {
    return (u & 0x80000000u) ? __uint_as_float(u & 0x7FFFFFFFu)
                             : __uint_as_float(~u);
}
__device__ __forceinline__ void split2(float x, float& h, float& l) {
    h = tf32f(x);
    l = tf32f(x - h);
}

// ======================================================================
// split-tf32 GEMM (3-MMA, exact): C = A[M,K] @ W[K,N] + bias.
// 128x128 tile, BK=32, 256 thr = 8 warps.
// Optional split-output epilogue: (acc+bias)*scale -> hi/lo planes.
// ======================================================================
#define GA 36
#define GB 136
#define GEMM_SMEM ((128*GA*2 + 32*GB*2) * 4)   // 71680 bytes

__device__ __forceinline__
void gemm_body(const float* __restrict__ A, const float* __restrict__ W,
               const float* __restrict__ bias,
               float* __restrict__ Ch, float* __restrict__ Cl, float scale,
               int M, int K, int N)
{
    extern __shared__ float gsm[];
    float* Ash = gsm;
    float* Asl = Ash + 128 * GA;
    float* Bsh = Asl + 128 * GA;
    float* Bsl = Bsh + 32 * GB;

    const int t    = threadIdx.x;
    const int m0   = blockIdx.y * 128;
    const int n0   = blockIdx.x * 128;
    const int w    = t >> 5;
    const int lane = t & 31;
    const int wm   = w >> 2;
    const int wn   = w & 3;
    const int grp  = lane >> 2;
    const int tg   = lane & 3;

    float acc[4][4][4];
#pragma unroll
    for (int i = 0; i < 4; ++i)
#pragma unroll
        for (int j = 0; j < 4; ++j)
#pragma unroll
            for (int c = 0; c < 4; ++c) acc[i][j][c] = 0.f;

    const float* Aptr = A + (size_t)m0 * K;
    const float* Wptr = W + n0;

    for (int k0 = 0; k0 < K; k0 += 32) {
#pragma unroll
        for (int i = 0; i < 4; ++i) {
            int idx = t + i * 256;
            int row = idx >> 3;
            int c4  = (idx & 7) * 4;
            float4 v = *(const float4*)(Aptr + (size_t)row * K + k0 + c4);
            float h0, l0, h1, l1, h2, l2, h3, l3;
            split2(v.x, h0, l0); split2(v.y, h1, l1);
            split2(v.z, h2, l2); split2(v.w, h3, l3);
            *(float4*)&Ash[row * GA + c4] = make_float4(h0, h1, h2, h3);
            *(float4*)&Asl[row * GA + c4] = make_float4(l0, l1, l2, l3);
        }
#pragma unroll
        for (int i = 0; i < 4; ++i) {
            int idx = t + i * 256;
            int row = idx >> 5;
            int c4  = (idx & 31) * 4;
            float4 v = *(const float4*)(Wptr + (size_t)(k0 + row) * N + c4);
            float h0, l0, h1, l1, h2, l2, h3, l3;
            split2(v.x, h0, l0); split2(v.y, h1, l1);
            split2(v.z, h2, l2); split2(v.w, h3, l3);
            *(float4*)&Bsh[row * GB + c4] = make_float4(h0, h1, h2, h3);
            *(float4*)&Bsl[row * GB + c4] = make_float4(l0, l1, l2, l3);
        }
        __syncthreads();

#pragma unroll
        for (int ks = 0; ks < 4; ++ks) {
            const int ka = ks * 8 + tg;
            unsigned bh[4][2], bl[4][2];
#pragma unroll
            for (int nt = 0; nt < 4; ++nt) {
                int c = wn * 32 + nt * 8 + grp;
                bh[nt][0] = fu(Bsh[ka * GB + c]);
                bh[nt][1] = fu(Bsh[(ka + 4) * GB + c]);
                bl[nt][0] = fu(Bsl[ka * GB + c]);
                bl[nt][1] = fu(Bsl[(ka + 4) * GB + c]);
            }
#pragma unroll
            for (int mt = 0; mt < 4; ++mt) {
                int r = wm * 64 + mt * 16 + grp;
                unsigned ah0 = fu(Ash[r * GA + ka]);
                unsigned ah1 = fu(Ash[(r + 8) * GA + ka]);
                unsigned ah2 = fu(Ash[r * GA + ka + 4]);
                unsigned ah3 = fu(Ash[(r + 8) * GA + ka + 4]);
                unsigned al0 = fu(Asl[r * GA + ka]);
                unsigned al1 = fu(Asl[(r + 8) * GA + ka]);
                unsigned al2 = fu(Asl[r * GA + ka + 4]);
                unsigned al3 = fu(Asl[(r + 8) * GA + ka + 4]);
#pragma unroll
                for (int nt = 0; nt < 4; ++nt) {
                    mma_tf32(acc[mt][nt], ah0, ah1, ah2, ah3, bh[nt][0], bh[nt][1]);
                    mma_tf32(acc[mt][nt], ah0, ah1, ah2, ah3, bl[nt][0], bl[nt][1]);
                    mma_tf32(acc[mt][nt], al0, al1, al2, al3, bh[nt][0], bh[nt][1]);
                }
            }
        }
        __syncthreads();
    }

    if (Cl == nullptr) {
#pragma unroll
        for (int nt = 0; nt < 4; ++nt) {
            const int c = n0 + wn * 32 + nt * 8 + 2 * tg;
            float2 bv = *(const float2*)&bias[c];
#pragma unroll
            for (int mt = 0; mt < 4; ++mt) {
                int r = m0 + wm * 64 + mt * 16 + grp;
                float2 r0 = make_float2(acc[mt][nt][0] + bv.x, acc[mt][nt][1] + bv.y);
                float2 r1 = make_float2(acc[mt][nt][2] + bv.x, acc[mt][nt][3] + bv.y);
                *(float2*)&Ch[(size_t)r * N + c]       = r0;
                *(float2*)&Ch[(size_t)(r + 8) * N + c] = r1;
            }
        }
    } else {
#pragma unroll
        for (int nt = 0; nt < 4; ++nt) {
            const int c = n0 + wn * 32 + nt * 8 + 2 * tg;
            float2 bv = *(const float2*)&bias[c];
#pragma unroll
            for (int mt = 0; mt < 4; ++mt) {
                int r = m0 + wm * 64 + mt * 16 + grp;
                float v00 = (acc[mt][nt][0] + bv.x) * scale;
                float v01 = (acc[mt][nt][1] + bv.y) * scale;
                float v10 = (acc[mt][nt][2] + bv.x) * scale;
                float v11 = (acc[mt][nt][3] + bv.y) * scale;
                float h00, l00, h01, l01, h10, l10, h11, l11;
                split2(v00, h00, l00); split2(v01, h01, l01);
                split2(v10, h10, l10); split2(v11, h11, l11);
                *(float2*)&Ch[(size_t)r * N + c]       = make_float2(h00, h01);
                *(float2*)&Ch[(size_t)(r + 8) * N + c] = make_float2(h10, h11);
                *(float2*)&Cl[(size_t)r * N + c]       = make_float2(l00, l01);
                *(float2*)&Cl[(size_t)(r + 8) * N + c] = make_float2(l10, l11);
            }
        }
    }
}

// ======================================================================
// single-tf32 GEMM (1-MMA, ~1.2e-4 rel err): used for the V projection
// only (V never enters top-k selection). Output rounded to tf32 so the
// attention kernel can skip its V cvt.
// ======================================================================
__device__ __forceinline__
void gemm1_body(const float* __restrict__ A, const float* __restrict__ W,
                const float* __restrict__ bias, float* __restrict__ C,
                int M, int K, int N)
{
    extern __shared__ float gsm[];
    float* As = gsm;                      // [128][GA] tf32
    float* Bs = gsm + 128 * GA;           // [32][GB] tf32

    const int t    = threadIdx.x;
    const int m0   = blockIdx.y * 128;
    const int n0   = blockIdx.x * 128;
    const int w    = t >> 5;
    const int lane = t & 31;
    const int wm   = w >> 2;
    const int wn   = w & 3;
    const int grp  = lane >> 2;
    const int tg   = lane & 3;

    float acc[4][4][4];
#pragma unroll
    for (int i = 0; i < 4; ++i)
#pragma unroll
        for (int j = 0; j < 4; ++j)
#pragma unroll
            for (int c = 0; c < 4; ++c) acc[i][j][c] = 0.f;

    const float* Aptr = A + (size_t)m0 * K;
    const float* Wptr = W + n0;

    for (int k0 = 0; k0 < K; k0 += 32) {
#pragma unroll
        for (int i = 0; i < 4; ++i) {
            int idx = t + i * 256;
            int row = idx >> 3;
            int c4  = (idx & 7) * 4;
            float4 v = *(const float4*)(Aptr + (size_t)row * K + k0 + c4);
            *(float4*)&As[row * GA + c4] =
                make_float4(tf32f(v.x), tf32f(v.y), tf32f(v.z), tf32f(v.w));
        }
#pragma unroll
        for (int i = 0; i < 4; ++i) {
            int idx = t + i * 256;
            int row = idx >> 5;
            int c4  = (idx & 31) * 4;
            float4 v = *(const float4*)(Wptr + (size_t)(k0 + row) * N + c4);
            *(float4*)&Bs[row * GB + c4] =
                make_float4(tf32f(v.x), tf32f(v.y), tf32f(v.z), tf32f(v.w));
        }
        __syncthreads();

#pragma unroll
        for (int ks = 0; ks < 4; ++ks) {
            const int ka = ks * 8 + tg;
            unsigned bh[4][2];
#pragma unroll
            for (int nt = 0; nt < 4; ++nt) {
                int c = wn * 32 + nt * 8 + grp;
                bh[nt][0] = fu(Bs[ka * GB + c]);
                bh[nt][1] = fu(Bs[(ka + 4) * GB + c]);
            }
#pragma unroll
            for (int mt = 0; mt < 4; ++mt) {
                int r = wm * 64 + mt * 16 + grp;
                unsigned ah0 = fu(As[r * GA + ka]);
                unsigned ah1 = fu(As[(r + 8) * GA + ka]);
                unsigned ah2 = fu(As[r * GA + ka + 4]);
                unsigned ah3 = fu(As[(r + 8) * GA + ka + 4]);
#pragma unroll
                for (int nt = 0; nt < 4; ++nt)
                    mma_tf32(acc[mt][nt], ah0, ah1, ah2, ah3, bh[nt][0], bh[nt][1]);
            }
        }
        __syncthreads();
    }

    // epilogue: bias add, then round to tf32 (attention reads V as tf32)
#pragma unroll
    for (int nt = 0; nt < 4; ++nt) {
        const int c = n0 + wn * 32 + nt * 8 + 2 * tg;
        float2 bv = *(const float2*)&bias[c];
#pragma unroll
        for (int mt = 0; mt < 4; ++mt) {
            int r = m0 + wm * 64 + mt * 16 + grp;
            float2 r0 = make_float2(tf32f(acc[mt][nt][0] + bv.x),
                                    tf32f(acc[mt][nt][1] + bv.y));
            float2 r1 = make_float2(tf32f(acc[mt][nt][2] + bv.x),
                                    tf32f(acc[mt][nt][3] + bv.y));
            *(float2*)&C[(size_t)r * N + c]       = r0;
            *(float2*)&C[(size_t)(r + 8) * N + c] = r1;
        }
    }
}

// ---- weight combination: grid (4, 4, 12) ----
__global__ __launch_bounds__(256, 2)
void combine_w(const float* __restrict__ emb_w,
               const float* __restrict__ Wq, const float* __restrict__ Wk,
               const float* __restrict__ Wv, const float* __restrict__ Wo)
{
    const int z = blockIdx.z;
    if (z < 9) {
        const int l = z / 3 + 1, j = z % 3;
        const float* Wsel = (j == 0 ? Wq : j == 1 ? Wk : Wv) + (size_t)l * E_ * E_;
        gemm_body(Wo + (size_t)(l - 1) * E_ * E_, Wsel, g_zero,
                  g_cw + (size_t)z * E_ * E_, nullptr, 1.f, E_, E_, E_);
    } else {
        if (blockIdx.y != 0) return;
        const int j = z - 9;
        const float* Wsel = (j == 0 ? Wq : j == 1 ? Wk : Wv);
        gemm_body(emb_w, Wsel, g_zero,
                  g_cw0 + (size_t)j * FIN * E_, nullptr, 1.f, FIN, E_, E_);
    }
}

__global__ void combine_b(const float* __restrict__ emb_b,
                          const float* __restrict__ Wq, const float* __restrict__ Wk,
                          const float* __restrict__ Wv,
                          const float* __restrict__ bq, const float* __restrict__ bk,
                          const float* __restrict__ bv, const float* __restrict__ bo)
{
    const int l = blockIdx.x / 3, j = blockIdx.x % 3;
    const int t = threadIdx.x;
    const float* W = (j == 0 ? Wq : j == 1 ? Wk : Wv) + (size_t)l * E_ * E_;
    const float* badd = (j == 0 ? bq : j == 1 ? bk : bv) + (size_t)l * E_;
    float s = 0.f;
    if (l == 0) {
        for (int k = 0; k < FIN; ++k) s += emb_b[k] * W[(size_t)k * E_ + t];
    } else {
        const float* bvp = bo + (size_t)(l - 1) * E_;
        for (int k = 0; k < E_; ++k) s += bvp[k] * W[(size_t)k * E_ + t];
    }
    g_cb[blockIdx.x * E_ + t] = s + badd[t];
}

__global__ void fc_fold(const float* __restrict__ Wo, const float* __restrict__ fc_w,
                        const float* __restrict__ fc_b, const float* __restrict__ bo)
{
    const int t = blockIdx.x * 1024 + threadIdx.x;
    const float* Wo3 = Wo + (size_t)3 * E_ * E_;
    if (t < E_ * NCLS) {
        const int i = t / NCLS, c = t % NCLS;
        float s = 0.f;
        for (int k = 0; k < E_; ++k)
            s += Wo3[(size_t)i * E_ + k] * fc_w[k * NCLS + c];
        g_fcw[t] = s;
    }
    if (t < NCLS) {
        const float* bo3 = bo + (size_t)3 * E_;
        float s = fc_b[t];
        for (int k = 0; k < E_; ++k)
            s += bo3[k] * fc_w[k * NCLS + t];
        g_fcb[t] = s;
    }
}

__global__ __launch_bounds__(256, 2)
void gemm_qkv_g(const float* __restrict__ A,
                const float* __restrict__ Wq_, const float* __restrict__ Wk_,
                const float* __restrict__ Wv_,
                const float* __restrict__ bq_, const float* __restrict__ bk_,
                const float* __restrict__ bv_, int K)
{
    if (blockIdx.z == 0)
        gemm_body(A, Wq_, bq_, g_qh, g_ql, 0.125f, B_ * S_, K, E_);
    else if (blockIdx.z == 1)
        gemm_body(A, Wk_, bk_, g_k, nullptr, 1.f, B_ * S_, K, E_);
    else
        gemm1_body(A, Wv_, bv_, g_v, B_ * S_, K, E_);   // V: 1-MMA, tf32 out
}

// ======================================================================
// Sparse attention (R15 + V already tf32): 512 threads = 16 warps.
//  phase1: S = Q K^T, exact split-tf32 (3 MMA) — top-k stays exact
//  phase2: exact top-k (early-exit) + softmax
//  phase3: O = P V, P single-tf32 cvt, V pre-rounded (no cvt), 1 MMA
// ======================================================================
#define SP   1028
#define QP   68
#define KPR  68
#define VPR  72

#define ST_F (32 * SP)
#define QS_F (32 * QP)
#define KV_F (256 * VPR)
#define ATTN_SMEM ((ST_F + 2 * QS_F + KV_F) * 4)   // 222720 bytes

__global__ __launch_bounds__(512, 1)
void attn_kernel()
{
    extern __shared__ float sm[];
    float* St  = sm;
    float* Qsh = sm + ST_F;
    float* Qsl = Qsh + QS_F;
    float* KV  = Qsl + QS_F;

    const int t    = threadIdx.x;
    const int w    = t >> 5;
    const int lane = t & 31;
    const int grp  = lane >> 2;
    const int tg   = lane & 3;

    const int gid = blockIdx.x;
    const int qt  = gid & 31;
    const int hh  = (gid >> 5) & 7;
    const int b   = gid >> 8;

    const size_t qoff = ((size_t)(b * S_ + qt * QT)) * E_ + hh * D_;
    const size_t koff = ((size_t)b * S_) * E_ + hh * D_;

    const float* Qh = g_qh + qoff;
    const float* Ql = g_ql + qoff;
    const float* Kg = g_k + koff;
    const float* Vg = g_v + koff;
    float*       Og = g_o + qoff;

    {
        const int qi = t >> 4;
        const int d0 = (t & 15) * 4;
        float4 h4 = *(const float4*)(Qh + (size_t)qi * E_ + d0);
        float4 l4 = *(const float4*)(Ql + (size_t)qi * E_ + d0);
        *(float4*)&Qsh[qi * QP + d0] = h4;
        *(float4*)&Qsl[qi * QP + d0] = l4;
    }

    {
        float* Ksm = KV;
        for (int kc = 0; kc < S_; kc += 256) {
#pragma unroll
            for (int i = 0; i < 8; ++i) {
                int idx = t + i * 512;
                int row = idx >> 4;
                int c4  = (idx & 15) * 4;
                *(float4*)&Ksm[row * KPR + c4] =
                    *(const float4*)(Kg + (size_t)(kc + row) * E_ + c4);
            }
            __syncthreads();

            float acc[2][2][4];
#pragma unroll
            for (int mt = 0; mt < 2; ++mt)
#pragma unroll
                for (int nt = 0; nt < 2; ++nt)
#pragma unroll
                    for (int c = 0; c < 4; ++c) acc[mt][nt][c] = 0.f;

#pragma unroll
            for (int ks = 0; ks < 8; ++ks) {
                const int ka = ks * 8 + tg;
                unsigned ah[2][4], al[2][4];
#pragma unroll
                for (int mt = 0; mt < 2; ++mt) {
                    const int r = mt * 16 + grp;
                    ah[mt][0] = fu(Qsh[r * QP + ka]);
                    ah[mt][1] = fu(Qsh[(r + 8) * QP + ka]);
                    ah[mt][2] = fu(Qsh[r * QP + ka + 4]);
                    ah[mt][3] = fu(Qsh[(r + 8) * QP + ka + 4]);
                    al[mt][0] = fu(Qsl[r * QP + ka]);
                    al[mt][1] = fu(Qsl[(r + 8) * QP + ka]);
                    al[mt][2] = fu(Qsl[r * QP + ka + 4]);
                    al[mt][3] = fu(Qsl[(r + 8) * QP + ka + 4]);
                }
                unsigned bh[2][2], bl[2][2];
#pragma unroll
                for (int nt = 0; nt < 2; ++nt) {
                    const int key = w * 16 + nt * 8 + grp;
                    float y0 = Ksm[key * KPR + ka];
                    float y1 = Ksm[key * KPR + ka + 4];
                    float h0, l0, h1, l1;
                    split2(y0, h0, l0); split2(y1, h1, l1);
                    bh[nt][0] = fu(h0); bh[nt][1] = fu(h1);
                    bl[nt][0] = fu(l0); bl[nt][1] = fu(l1);
                }
#pragma unroll
                for (int mt = 0; mt < 2; ++mt)
#pragma unroll
                    for (int nt = 0; nt < 2; ++nt) {
                        mma_tf32(acc[mt][nt], ah[mt][0], ah[mt][1], ah[mt][2], ah[mt][3],
                                 bh[nt][0], bh[nt][1]);
                        mma_tf32(acc[mt][nt], ah[mt][0], ah[mt][1], ah[mt][2], ah[mt][3],
                                 bl[nt][0], bl[nt][1]);
                        mma_tf32(acc[mt][nt], al[mt][0], al[mt][1], al[mt][2], al[mt][3],
                                 bh[nt][0], bh[nt][1]);
                    }
            }
            const int keyb = kc + w * 16;
#pragma unroll
            for (int mt = 0; mt < 2; ++mt)
#pragma unroll
                for (int nt = 0; nt < 2; ++nt) {
                    const int q = mt * 16 + grp;
                    const int k = keyb + nt * 8 + 2 * tg;
                    *(float2*)&St[(size_t)q * SP + k] =
                        make_float2(acc[mt][nt][0], acc[mt][nt][1]);
                    *(float2*)&St[(size_t)(q + 8) * SP + k] =
                        make_float2(acc[mt][nt][2], acc[mt][nt][3]);
                }
            __syncthreads();
        }
    }

#pragma unroll
    for (int qq = 0; qq < 2; ++qq) {
        const int qi = w * 2 + qq;
        float* row = St + (size_t)qi * SP;

        unsigned u[32];
        unsigned umax = 0u, umin = 0xFFFFFFFFu;
#pragma unroll
        for (int i = 0; i < 32; ++i) {
            u[i] = fmap(row[lane + 32 * i]);
            umax = max(umax, u[i]);
            umin = min(umin, u[i]);
        }
        umax = __reduce_max_sync(0xFFFFFFFFu, umax);
        umin = __reduce_min_sync(0xFFFFFFFFu, umin);

        unsigned lo = umin, hi = umax, thr;
        for (;;) {
            if (lo >= hi) { thr = lo; break; }
            unsigned mid = lo + ((hi - lo + 1) >> 1);
            unsigned c = 0;
#pragma unroll
            for (int i = 0; i < 32; ++i) c += (u[i] >= mid);
            c = __reduce_add_sync(0xFFFFFFFFu, c);
            if (c == KTOP) { thr = mid; break; }
            if (c > KTOP) lo = mid; else hi = mid - 1;
        }
        const float mf = unfmap(umax);

        float sum = 0.f;
#pragma unroll
        for (int i = 0; i < 32; ++i) {
            float ev = 0.f;
            if (u[i] >= thr) ev = __expf(unfmap(u[i]) - mf);
            u[i] = __float_as_uint(ev);
            sum += ev;
        }
#pragma unroll
        for (int off = 16; off > 0; off >>= 1)
            sum += __shfl_xor_sync(0xFFFFFFFFu, sum, off);
        const float inv = 1.f / sum;

#pragma unroll
        for (int i = 0; i < 32; ++i)
            row[lane + 32 * i] = __uint_as_float(u[i]) * inv;
    }
    __syncthreads();

    // ---- phase 3: O = P V ; P tf32 cvt, V pre-rounded; 1 MMA/frag ----
    {
        float* Vsm = KV;
        const int kg = w >> 2;
        const int wn = w & 3;

        float acc[2][2][4];
#pragma unroll
        for (int mt = 0; mt < 2; ++mt)
#pragma unroll
            for (int nt = 0; nt < 2; ++nt)
#pragma unroll
                for (int c = 0; c < 4; ++c) acc[mt][nt][c] = 0.f;

        for (int kc = 0; kc < S_; kc += 256) {
#pragma unroll
            for (int i = 0; i < 8; ++i) {
                int idx = t + i * 512;
                int row = idx >> 4;
                int c4  = (idx & 15) * 4;
                *(float4*)&Vsm[row * VPR + c4] =
                    *(const float4*)(Vg + (size_t)(kc + row) * E_ + c4);
            }
            __syncthreads();

#pragma unroll
            for (int ks = 0; ks < 8; ++ks) {
                const int kl = kg * 64 + ks * 8;
                const int k0 = kc + kl;

                unsigned bh[2][2];
#pragma unroll
                for (int nt = 0; nt < 2; ++nt) {
                    const int col = wn * 16 + nt * 8 + grp;
                    bh[nt][0] = fu(Vsm[(kl + tg) * VPR + col]);      // already tf32
                    bh[nt][1] = fu(Vsm[(kl + tg + 4) * VPR + col]);
                }
#pragma unroll
                for (int mt = 0; mt < 2; ++mt) {
                    unsigned ah0 = fu(tf32f(St[(mt * 16 + grp) * SP + k0 + tg]));
                    unsigned ah1 = fu(tf32f(St[(mt * 16 + grp + 8) * SP + k0 + tg]));
                    unsigned ah2 = fu(tf32f(St[(mt * 16 + grp) * SP + k0 + tg + 4]));
                    unsigned ah3 = fu(tf32f(St[(mt * 16 + grp + 8) * SP + k0 + tg + 4]));
#pragma unroll
                    for (int nt = 0; nt < 2; ++nt)
                        mma_tf32(acc[mt][nt], ah0, ah1, ah2, ah3, bh[nt][0], bh[nt][1]);
                }
            }
            __syncthreads();
        }

        float* red = KV;
#pragma unroll
        for (int mt = 0; mt < 2; ++mt)
#pragma unroll
            for (int nt = 0; nt < 2; ++nt) {
                const int q = mt * 16 + grp;
                const int d = wn * 16 + nt * 8 + 2 * tg;
                *(float2*)&red[kg * 2176 + q * 68 + d] =
                    make_float2(acc[mt][nt][0], acc[mt][nt][1]);
                *(float2*)&red[kg * 2176 + (q + 8) * 68 + d] =
                    make_float2(acc[mt][nt][2], acc[mt][nt][3]);
            }
        __syncthreads();

#pragma unroll
        for (int kk = 0; kk < 4; ++kk) {
            int m  = t + kk * 512;
            int qi = m >> 6, dd = m & 63;
            float s = red[0 * 2176 + qi * 68 + dd] + red[1 * 2176 + qi * 68 + dd]
                    + red[2 * 2176 + qi * 68 + dd] + red[3 * 2176 + qi * 68 + dd];
            Og[(size_t)qi * E_ + dd] = s;
        }
    }
}

// ======================================================================
// mean pool + final FC
// ======================================================================
__global__ void meanpool_k(const float* __restrict__ h, float* __restrict__ pool)
{
    __shared__ float red[512];
    const int b = blockIdx.y;
    const int e = blockIdx.x * 128 + (threadIdx.x & 127);
    const int slice = threadIdx.x >> 7;
    const float* base = h + (size_t)b * S_ * E_ + e;
    float s = 0.f;
#pragma unroll 8
    for (int i = 0; i < 256; ++i)
        s += base[(size_t)(slice * 256 + i) * E_];
    red[threadIdx.x] = s;
    __syncthreads();
    if (slice == 0) {
        float tot = red[threadIdx.x] + red[threadIdx.x + 128] +
                    red[threadIdx.x + 256] + red[threadIdx.x + 384];
        pool[b * E_ + e] = tot * (1.f / (float)S_);
    }
}

__global__ void fc_k(const float* __restrict__ pool, const float* __restrict__ w,
                     const float* __restrict__ bias, float* __restrict__ out)
{
    int t = threadIdx.x;
    if (t >= B_ * NCLS) return;
    int b = t / NCLS, c = t % NCLS;
    float s = bias[c];
    const float* p = pool + b * E_;
#pragma unroll 8
    for (int k = 0; k < E_; ++k)
        s += p[k] * w[k * NCLS + c];
    out[t] = s;
}

// ======================================================================
// launch
// ======================================================================
extern "C" void kernel_launch(void* const* d_in, const int* in_sizes, int n_in,
                              void* d_out, int out_size)
{
    (void)in_sizes; (void)n_in; (void)out_size;

    const float* x     = (const float*)d_in[0];
    const float* emb_w = (const float*)d_in[1];
    const float* emb_b = (const float*)d_in[2];
    const float* Wq    = (const float*)d_in[3];
    const float* Wk    = (const float*)d_in[4];
    const float* Wv    = (const float*)d_in[5];
    const float* Wo    = (const float*)d_in[6];
    const float* bq    = (const float*)d_in[7];
    const float* bk    = (const float*)d_in[8];
    const float* bv    = (const float*)d_in[9];
    const float* bo    = (const float*)d_in[10];
    const float* fc_w  = (const float*)d_in[11];
    const float* fc_b  = (const float*)d_in[12];
    float* out = (float*)d_out;

    float *o, *pool, *cw0, *cw, *cb, *fcw, *fcb;
    cudaGetSymbolAddress((void**)&o,    g_o);
    cudaGetSymbolAddress((void**)&pool, g_pool);
    cudaGetSymbolAddress((void**)&cw0,  g_cw0);
    cudaGetSymbolAddress((void**)&cw,   g_cw);
    cudaGetSymbolAddress((void**)&cb,   g_cb);
    cudaGetSymbolAddress((void**)&fcw,  g_fcw);
    cudaGetSymbolAddress((void**)&fcb,  g_fcb);

    cudaFuncSetAttribute(attn_kernel, cudaFuncAttributeMaxDynamicSharedMemorySize, ATTN_SMEM);
    cudaFuncSetAttribute(gemm_qkv_g,  cudaFuncAttributeMaxDynamicSharedMemorySize, GEMM_SMEM);
    cudaFuncSetAttribute(combine_w,   cudaFuncAttributeMaxDynamicSharedMemorySize, GEMM_SMEM);

    const int M = B_ * S_;                          // 8192
    dim3 qkvgrid(E_ / 128, M / 128, 3);             // (4, 64, 3)
    const int attn_grid = B_ * H_ * (S_ / QT);      // 2048

    // ---- weight/bias folding ----
    combine_w<<<dim3(4, 4, 12), 256, GEMM_SMEM>>>(emb_w, Wq, Wk, Wv, Wo);
    combine_b<<<12, E_>>>(emb_b, Wq, Wk, Wv, bq, bk, bv, bo);
    fc_fold<<<5, 1024>>>(Wo, fc_w, fc_b, bo);

    // ---- layer 0: QKV directly from x (K = FIN = 128) ----
    gemm_qkv_g<<<qkvgrid, 256, GEMM_SMEM>>>(
        x, cw0, cw0 + FIN * E_, cw0 + 2 * FIN * E_,
        cb, cb + E_, cb + 2 * E_, FIN);
    attn_kernel<<<attn_grid, 512, ATTN_SMEM>>>();

    // ---- layers 1..3: QKV from o with folded Wo (K = 512) ----
    for (int l = 1; l < L_; ++l) {
        const size_t wb = (size_t)(l - 1) * 3 * E_ * E_;
        const size_t bb = (size_t)l * 3 * E_;
        gemm_qkv_g<<<qkvgrid, 256, GEMM_SMEM>>>(
            o, cw + wb, cw + wb + (size_t)E_ * E_, cw + wb + (size_t)2 * E_ * E_,
            cb + bb, cb + bb + E_, cb + bb + 2 * E_, E_);
        attn_kernel<<<attn_grid, 512, ATTN_SMEM>>>();
    }

    // ---- pool over o3, FC with folded weights ----
    meanpool_k<<<dim3(E_ / 128, B_), 512>>>(o, pool);
    fc_k<<<1, 128>>>(pool, fcw, fcb, out);
}